// round 7
// baseline (speedup 1.0000x reference)
#include <cuda_runtime.h>
#include <cstdint>

// ============================================================================
// ESF_78391743086936 — algebraic restructure + legacy mma.sync TF32 GEMMs
// (tcgen05 is NOT available: harness ptxas targets sm_103 without 'a').
//   u      = global @ Wu + b_u ;  Wu = Wq Wk^T, b_u = Wk bq   (bk cancels)
//   a2     = softmax_k( (local_k . u) / 16 )
//   pooled = sum_k a2[k] local[k]
//   out    = relu( [pooled|global] @ [Wl;Wg] + c ) + lf_mean + b_dr + global
//   Wl = Wv Wf[:H], Wg = Sw * Wv Wf[H:], c = folded biases, Sw = sum w_dr
// GEMM core: m16n8k8 TF32 mma.sync, 128x256 block / 64x64 warp tiles,
// 3-stage cp.async pipeline.
// ============================================================================

constexpr int F  = 512;
constexpr int H  = 256;
constexpr int NL = 12;
constexpr int MAXB = 16384;

// GEMM tiling
constexpr int BM = 128, BN = 256, BK = 32, TH = 256, STAGES = 3;
constexpr int A_WORDS = BM * 36;            // padded stride 36
constexpr int B_WORDS = BN * 36;
constexpr int STAGE_WORDS = A_WORDS + B_WORDS;       // 13824
constexpr int SMEM_SZ = STAGES * STAGE_WORDS * 4;    // 165888 B
constexpr int A_BYTES_ST = A_WORDS * 4;
constexpr int STAGE_BYTES = STAGE_WORDS * 4;

// ---- device scratch (__device__ globals; no allocs allowed) ----
__device__ uint32_t g_gtf[(size_t)MAXB * F];   // gfeat  as tf32 (rna)
__device__ uint32_t g_ptf[(size_t)MAXB * F];   // pooled as tf32 (rna)
__device__ float    g_U  [(size_t)MAXB * F];   // u = g@Wu + b_u
__device__ float    g_resid[(size_t)MAXB * F]; // lf_mean + b_dr + global
__device__ uint32_t g_Wu [F * F];              // [n=f'][k=f]  (Wu^T) tf32
__device__ uint32_t g_Wc [F * 2 * F];          // [n=f'][k: 0..511 Wl^T | 512..1023 Wg^T]
__device__ uint32_t g_Wq32[F * H], g_Wk32[F * H], g_Wv32[F * H];
__device__ uint32_t g_WfT[F * F];              // WfT[f'][h2] = Wf[h2][f'] tf32
__device__ float    g_biasU[F], g_biasC[F];

// ---------------- helpers ----------------
__device__ __forceinline__ uint32_t f2tf(float x) {
    uint32_t u; asm("cvt.rna.tf32.f32 %0, %1;" : "=r"(u) : "f"(x)); return u;
}
__device__ __forceinline__ uint32_t s2u(const void* p) {
    uint32_t a;
    asm("{ .reg .u64 t; cvta.to.shared.u64 t, %1; cvt.u32.u64 %0, t; }"
        : "=r"(a) : "l"(p));
    return a;
}
__device__ __forceinline__ void cp16(uint32_t dst, const void* src) {
    asm volatile("cp.async.cg.shared.global [%0], [%1], 16;"
                 :: "r"(dst), "l"(src) : "memory");
}
__device__ __forceinline__ void cp_commit() {
    asm volatile("cp.async.commit_group;" ::: "memory");
}
__device__ __forceinline__ void cp_wait2() {
    asm volatile("cp.async.wait_group 2;" ::: "memory");
}
__device__ __forceinline__ void mma_tf32(float* d, const uint32_t* a, const uint32_t* b) {
    asm volatile(
        "mma.sync.aligned.m16n8k8.row.col.f32.tf32.tf32.f32 "
        "{%0,%1,%2,%3}, {%4,%5,%6,%7}, {%8,%9}, {%0,%1,%2,%3};\n"
        : "+f"(d[0]), "+f"(d[1]), "+f"(d[2]), "+f"(d[3])
        : "r"(a[0]), "r"(a[1]), "r"(a[2]), "r"(a[3]), "r"(b[0]), "r"(b[1]));
}

// ============================================================================
// Prep kernels
// ============================================================================
__global__ void g_cvt_kernel(const float4* __restrict__ src, uint4* __restrict__ dst, int n4) {
    int i = blockIdx.x * 256 + threadIdx.x;
    if (i < n4) {
        float4 v = src[i];
        dst[i] = make_uint4(f2tf(v.x), f2tf(v.y), f2tf(v.z), f2tf(v.w));
    }
}

__global__ void w_cvt_kernel(const float* __restrict__ Wq, const float* __restrict__ Wk,
                             const float* __restrict__ Wv) {
    int i = blockIdx.x * 256 + threadIdx.x;   // covers 3*F*H
    int m = i / (F * H), r = i % (F * H);
    if (m == 0) g_Wq32[r] = f2tf(Wq[r]);
    else if (m == 1) g_Wk32[r] = f2tf(Wk[r]);
    else g_Wv32[r] = f2tf(Wv[r]);
}

__global__ void wf_transpose_kernel(const float* __restrict__ Wf) {
    __shared__ float t[32][33];
    int x = blockIdx.x * 32 + threadIdx.x;          // col f'
    int y0 = blockIdx.y * 32;                       // row h2
    for (int j = threadIdx.y; j < 32; j += 8)
        t[j][threadIdx.x] = Wf[(size_t)(y0 + j) * F + x];
    __syncthreads();
    int xo = blockIdx.y * 32 + threadIdx.x;         // WfT col = h2
    int yo = blockIdx.x * 32;                       // WfT row = f'
    for (int j = threadIdx.y; j < 32; j += 8)
        g_WfT[(size_t)(yo + j) * F + xo] = f2tf(t[threadIdx.x][j]);
}

__global__ void k0_bias_kernel(const float* __restrict__ Wk, const float* __restrict__ bq,
                               const float* __restrict__ bv, const float* __restrict__ wdr,
                               const float* __restrict__ bdr_p, const float* __restrict__ Wf,
                               const float* __restrict__ bf) {
    int tid = blockIdx.x * blockDim.x + threadIdx.x;
    float Sw = 0.f;
#pragma unroll
    for (int k = 0; k < NL; k++) Sw += wdr[k];
    float bdr = bdr_p[0];
    if (tid < F) {
        float s = 0.f;
        for (int h = 0; h < H; h++) s += Wk[tid * H + h] * bq[h];
        g_biasU[tid] = s;
    } else if (tid < 2 * F) {
        int f = tid - F;
        float s = bf[f];
        for (int h = 0; h < H; h++) {
            s += bv[h] * Wf[h * F + f];
            s += (Sw * bv[h] + bdr) * Wf[(H + h) * F + f];
        }
        g_biasC[f] = s;
    }
}

// ============================================================================
// Core GEMM: C[m][n] = sum_k A[m][k] * B[n][k]   (A row-major, B = W^T rows)
// Block 128x256, 8 warps (2m x 4n), warp tile 64x64, BK=32, 3-stage cp.async.
// EPI 0: g_U[r*512+c] = acc + biasU[c]
// EPI 1: out[r*512+c] = relu(acc + biasC[c]) + resid[r*512+c]
// EPI 2: weight fusion, z-batched (blockIdx.z selects job), writes tf32 bits.
// ============================================================================
template<int EPI>
__global__ void __launch_bounds__(TH, 1)
gemm_mma(const uint32_t* __restrict__ A, const uint32_t* __restrict__ A2,
         int splitChunk, int Astride,
         const uint32_t* __restrict__ Bmat, int Bstride, int Kchunks,
         void* __restrict__ outp, int outStride,
         const float* __restrict__ bias, const float* __restrict__ residp,
         const float* __restrict__ wdrp)
{
    extern __shared__ uint32_t sm[];
    const uint32_t sb = s2u(sm);
    const int tid = threadIdx.x, warp = tid >> 5, lane = tid & 31;
    const int wm = (warp & 1) * 64, wn = (warp >> 1) * 64;
    const int bn = blockIdx.x * BN, bm = blockIdx.y * BM;

    // weight-fusion job select (all operands are device globals)
    int colOff = 0;
    float scale = 1.f;
    if (EPI == 2) {
        int z = blockIdx.z;
        if (z == 0) { A = g_Wk32; Astride = H; Bmat = g_Wq32;
                      outp = (void*)g_Wu; outStride = F; }
        else        { A = g_WfT + (z == 2 ? H : 0); Astride = F; Bmat = g_Wv32;
                      outp = (void*)g_Wc; outStride = 2 * F;
                      colOff = (z == 2) ? F : 0; }
        Bstride = H; Kchunks = H / BK; splitChunk = 1 << 30;
        if (z == 2) {
            scale = 0.f;
#pragma unroll
            for (int k = 0; k < NL; k++) scale += wdrp[k];
        }
    }

    float acc[4][8][4];
#pragma unroll
    for (int i = 0; i < 4; i++)
#pragma unroll
        for (int j = 0; j < 8; j++)
#pragma unroll
            for (int v = 0; v < 4; v++) acc[i][j][v] = 0.f;

    auto issue_stage = [&](int c) {
        const int slot = c % STAGES;
        const uint32_t aBase = sb + slot * STAGE_BYTES;
        const uint32_t bBase = aBase + A_BYTES_ST;
        const uint32_t* Ap = A; int kloc = c * BK;
        if (c >= splitChunk) { Ap = A2; kloc = (c - splitChunk) * BK; }
#pragma unroll
        for (int j = 0; j < 4; j++) {                 // A: 1024 x 16B
            int i = tid + TH * j, m = i >> 3, cc = i & 7;
            cp16(aBase + m * 144 + cc * 16,
                 Ap + (size_t)(bm + m) * Astride + kloc + cc * 4);
        }
#pragma unroll
        for (int j = 0; j < 8; j++) {                 // B: 2048 x 16B
            int i = tid + TH * j, n = i >> 3, cc = i & 7;
            cp16(bBase + n * 144 + cc * 16,
                 Bmat + (size_t)(bn + n) * Bstride + c * BK + cc * 4);
        }
    };

    // prologue: stages 0, 1
    issue_stage(0); cp_commit();
    issue_stage(1); cp_commit();

    for (int c = 0; c < Kchunks; c++) {
        if (c + 2 < Kchunks) issue_stage(c + 2);
        cp_commit();                       // commit (possibly empty) group
        cp_wait2();                        // stage c complete (per-thread)
        __syncthreads();                   // visible block-wide

        const uint32_t* As = sm + (c % STAGES) * STAGE_WORDS;
        const uint32_t* Bs = As + A_WORDS;
#pragma unroll
        for (int kk = 0; kk < BK; kk += 8) {
            uint32_t af[4][4], bfr[8][2];
#pragma unroll
            for (int mf = 0; mf < 4; mf++) {
                int r0 = wm + mf * 16 + (lane >> 2);
                int c0 = kk + (lane & 3);
                af[mf][0] = As[r0 * 36 + c0];
                af[mf][1] = As[(r0 + 8) * 36 + c0];
                af[mf][2] = As[r0 * 36 + c0 + 4];
                af[mf][3] = As[(r0 + 8) * 36 + c0 + 4];
            }
#pragma unroll
            for (int nf = 0; nf < 8; nf++) {
                int n0 = wn + nf * 8 + (lane >> 2);
                int k0 = kk + (lane & 3);
                bfr[nf][0] = Bs[n0 * 36 + k0];
                bfr[nf][1] = Bs[n0 * 36 + k0 + 4];
            }
#pragma unroll
            for (int mf = 0; mf < 4; mf++)
#pragma unroll
                for (int nf = 0; nf < 8; nf++)
                    mma_tf32(acc[mf][nf], af[mf], bfr[nf]);
        }
        __syncthreads();                   // protect slot before re-fill
    }

    // ---- epilogue ----
#pragma unroll
    for (int mf = 0; mf < 4; mf++) {
        int r0 = bm + wm + mf * 16 + (lane >> 2);
#pragma unroll
        for (int nf = 0; nf < 8; nf++) {
            int c0 = bn + wn + nf * 8 + ((lane & 3) << 1);
#pragma unroll
            for (int half = 0; half < 2; half++) {
                int r = r0 + 8 * half;
                float d0 = acc[mf][nf][2 * half + 0];
                float d1 = acc[mf][nf][2 * half + 1];
                if (EPI == 0) {
                    float2 bu = *reinterpret_cast<const float2*>(bias + c0);
                    *reinterpret_cast<float2*>((float*)outp + (size_t)r * outStride + c0) =
                        make_float2(d0 + bu.x, d1 + bu.y);
                } else if (EPI == 1) {
                    float2 bc = *reinterpret_cast<const float2*>(bias + c0);
                    float2 rs = *reinterpret_cast<const float2*>(residp + (size_t)r * F + c0);
                    *reinterpret_cast<float2*>((float*)outp + (size_t)r * outStride + c0) =
                        make_float2(fmaxf(d0 + bc.x, 0.f) + rs.x,
                                    fmaxf(d1 + bc.y, 0.f) + rs.y);
                } else {
                    *reinterpret_cast<uint2*>((uint32_t*)outp +
                        (size_t)r * outStride + colOff + c0) =
                        make_uint2(f2tf(d0 * scale), f2tf(d1 * scale));
                }
            }
        }
    }
}

// ============================================================================
// K2: per-row attention over 12 local tokens (HBM-bound streaming pass).
// ============================================================================
__global__ void k2_attn_kernel(const float* __restrict__ gfeat,
                               const float* __restrict__ lfeat,
                               const float* __restrict__ wdr,
                               const float* __restrict__ bdr_p)
{
    const int b = blockIdx.x;
    const int t = threadIdx.x;     // 128
    const int f0 = t * 4;
    const float* lb = lfeat + (size_t)b * NL * F;

    float4 u4 = *reinterpret_cast<const float4*>(&g_U[(size_t)b * F + f0]);

    float4 loc[NL];
    float part[NL];
#pragma unroll
    for (int k = 0; k < NL; k++) {
        loc[k] = *reinterpret_cast<const float4*>(&lb[k * F + f0]);
        part[k] = loc[k].x * u4.x + loc[k].y * u4.y + loc[k].z * u4.z + loc[k].w * u4.w;
    }
#pragma unroll
    for (int k = 0; k < NL; k++) {
#pragma unroll
        for (int o = 16; o > 0; o >>= 1)
            part[k] += __shfl_xor_sync(0xffffffffu, part[k], o);
    }
    __shared__ float red[4][NL];
    const int lane = t & 31, w = t >> 5;
    if (lane == 0) {
#pragma unroll
        for (int k = 0; k < NL; k++) red[w][k] = part[k];
    }
    __syncthreads();

    float a2[NL];
    float m = -1e30f;
#pragma unroll
    for (int k = 0; k < NL; k++) {
        a2[k] = (red[0][k] + red[1][k] + red[2][k] + red[3][k]) * 0.0625f; // 1/sqrt(256)
        m = fmaxf(m, a2[k]);
    }
    float s = 0.f;
#pragma unroll
    for (int k = 0; k < NL; k++) { a2[k] = __expf(a2[k] - m); s += a2[k]; }
    const float inv = 1.f / s;

    float4 pool = make_float4(0.f, 0.f, 0.f, 0.f);
    float4 lfm  = make_float4(0.f, 0.f, 0.f, 0.f);
#pragma unroll
    for (int k = 0; k < NL; k++) {
        float a  = a2[k] * inv;
        float wd = wdr[k];
        pool.x += a * loc[k].x;  pool.y += a * loc[k].y;
        pool.z += a * loc[k].z;  pool.w += a * loc[k].w;
        lfm.x  += wd * loc[k].x; lfm.y  += wd * loc[k].y;
        lfm.z  += wd * loc[k].z; lfm.w  += wd * loc[k].w;
    }
    float4 g4 = *reinterpret_cast<const float4*>(&gfeat[(size_t)b * F + f0]);
    const float bdr = bdr_p[0];
    *reinterpret_cast<uint4*>(&g_ptf[(size_t)b * F + f0]) =
        make_uint4(f2tf(pool.x), f2tf(pool.y), f2tf(pool.z), f2tf(pool.w));
    *reinterpret_cast<float4*>(&g_resid[(size_t)b * F + f0]) =
        make_float4(lfm.x + bdr + g4.x, lfm.y + bdr + g4.y,
                    lfm.z + bdr + g4.z, lfm.w + bdr + g4.w);
}

// ============================================================================
extern "C" void kernel_launch(void* const* d_in, const int* in_sizes, int n_in,
                              void* d_out, int out_size)
{
    const float* gfeat = (const float*)d_in[0];
    const float* lfeat = (const float*)d_in[1];
    const float* Wq    = (const float*)d_in[2];
    const float* bq    = (const float*)d_in[3];
    const float* Wk    = (const float*)d_in[4];
    // d_in[5] (bk) cancels in the length-12 softmax.
    const float* Wv    = (const float*)d_in[6];
    const float* bv    = (const float*)d_in[7];
    const float* wdr   = (const float*)d_in[8];
    const float* bdr   = (const float*)d_in[9];
    const float* Wf    = (const float*)d_in[10];
    const float* bf    = (const float*)d_in[11];
    float* out = (float*)d_out;

    const int B = in_sizes[0] / F;   // 16384

    cudaFuncSetAttribute(gemm_mma<0>, cudaFuncAttributeMaxDynamicSharedMemorySize, SMEM_SZ);
    cudaFuncSetAttribute(gemm_mma<1>, cudaFuncAttributeMaxDynamicSharedMemorySize, SMEM_SZ);
    cudaFuncSetAttribute(gemm_mma<2>, cudaFuncAttributeMaxDynamicSharedMemorySize, SMEM_SZ);

    uint32_t* pWu  = nullptr; cudaGetSymbolAddress((void**)&pWu,  g_Wu);
    uint32_t* pWc  = nullptr; cudaGetSymbolAddress((void**)&pWc,  g_Wc);
    uint32_t* pGtf = nullptr; cudaGetSymbolAddress((void**)&pGtf, g_gtf);
    uint32_t* pPtf = nullptr; cudaGetSymbolAddress((void**)&pPtf, g_ptf);
    float*    pU   = nullptr; cudaGetSymbolAddress((void**)&pU,   g_U);
    float*    pRes = nullptr; cudaGetSymbolAddress((void**)&pRes, g_resid);
    float*    pBU  = nullptr; cudaGetSymbolAddress((void**)&pBU,  g_biasU);
    float*    pBC  = nullptr; cudaGetSymbolAddress((void**)&pBC,  g_biasC);

    // --- prep ---
    const int n4 = B * F / 4;
    g_cvt_kernel<<<(n4 + 255) / 256, 256>>>((const float4*)gfeat, (uint4*)pGtf, n4);
    w_cvt_kernel<<<3 * F * H / 256, 256>>>(Wq, Wk, Wv);
    wf_transpose_kernel<<<dim3(16, 16), dim3(32, 8)>>>(Wf);
    k0_bias_kernel<<<4, 256>>>(Wk, bq, bv, wdr, bdr, Wf, bf);

    // weight fusion: z=0 Wu^T, z=1 Wl^T, z=2 Wg^T (scaled by Sw)
    gemm_mma<2><<<dim3(F / BN, F / BM, 3), TH, SMEM_SZ>>>(
        nullptr, nullptr, 0, 0, nullptr, 0, 0, nullptr, 0,
        nullptr, nullptr, wdr);

    // --- main path ---
    // GEMM1: U = gfeat_tf @ Wu + b_u     (K=512 -> 16 chunks, N=512)
    gemm_mma<0><<<dim3(F / BN, B / BM), TH, SMEM_SZ>>>(
        pGtf, pGtf, 1 << 30, F, pWu, F, F / BK,
        pU, F, pBU, nullptr, nullptr);
    // K2: softmax over 12 locals -> pooled (tf32) + resid
    k2_attn_kernel<<<B, 128>>>(gfeat, lfeat, wdr, bdr);
    // GEMM2: out = relu([pooled|gfeat] @ Wc + c) + resid   (K=1024 -> 32 chunks)
    gemm_mma<1><<<dim3(F / BN, B / BM), TH, SMEM_SZ>>>(
        pPtf, pGtf, F / BK, F, pWc, 2 * F, 2 * F / BK,
        out, F, pBC, pRes, nullptr);
}

// round 10
// speedup vs baseline: 1.6365x; 1.6365x over previous
#include <cuda_runtime.h>
#include <cstdint>

// ============================================================================
// ESF_78391743086936 — algebraic restructure + legacy mma.sync TF32 GEMMs.
//   u      = global @ Wu + b_u ;  Wu = Wq Wk^T, b_u = Wk bq   (bk cancels)
//   a2     = softmax_k( (local_k . u) / 16 )
//   pooled = sum_k a2[k] local[k]
//   out    = relu( [pooled|global] @ [Wl;Wg] + c ) + lf_mean + b_dr + global
//   Wl = Wv Wf[:H], Wg = Sw * Wv Wf[H:], c = folded biases, Sw = sum w_dr
// R8: 2 CTAs/SM GEMM (BN=128, 110KB smem), fp32-bit truncation feeds tf32
// MMA directly (no cvt pre-passes), parallel bias kernel.
// ============================================================================

constexpr int F  = 512;
constexpr int H  = 256;
constexpr int NL = 12;
constexpr int MAXB = 16384;

// GEMM tiling: block 128x128, 8 warps (2m x 4n), warp tile 64x32, BK=32.
constexpr int BM = 128, BN = 128, BK = 32, TH = 256, STAGES = 3;
constexpr int A_WORDS = BM * 36;                     // padded stride 36
constexpr int B_WORDS = BN * 36;
constexpr int STAGE_WORDS = A_WORDS + B_WORDS;       // 9216
constexpr int SMEM_SZ = STAGES * STAGE_WORDS * 4;    // 110592 B -> 2 CTAs/SM
constexpr int A_BYTES_ST = A_WORDS * 4;
constexpr int STAGE_BYTES = STAGE_WORDS * 4;

// ---- device scratch ----
__device__ float    g_pooled[(size_t)MAXB * F];
__device__ float    g_U  [(size_t)MAXB * F];    // u = g@Wu + b_u
__device__ float    g_resid[(size_t)MAXB * F];  // lf_mean + b_dr + global
__device__ uint32_t g_Wu [F * F];               // [n=f'][k=f] (Wu^T) tf32
__device__ uint32_t g_Wc [F * 2 * F];           // [n=f'][0:512 Wl^T | 512:1024 Wg^T]
__device__ uint32_t g_WfT[F * F];               // WfT[f'][h2] = Wf[h2][f'] raw f32 bits
__device__ float    g_biasU[F], g_biasC[F];

// ---------------- helpers ----------------
__device__ __forceinline__ uint32_t f2tf(float x) {
    uint32_t u; asm("cvt.rna.tf32.f32 %0, %1;" : "=r"(u) : "f"(x)); return u;
}
__device__ __forceinline__ uint32_t s2u(const void* p) {
    uint32_t a;
    asm("{ .reg .u64 t; cvta.to.shared.u64 t, %1; cvt.u32.u64 %0, t; }"
        : "=r"(a) : "l"(p));
    return a;
}
__device__ __forceinline__ void cp16(uint32_t dst, const void* src) {
    asm volatile("cp.async.cg.shared.global [%0], [%1], 16;"
                 :: "r"(dst), "l"(src) : "memory");
}
__device__ __forceinline__ void cp_commit() {
    asm volatile("cp.async.commit_group;" ::: "memory");
}
__device__ __forceinline__ void cp_wait2() {
    asm volatile("cp.async.wait_group 2;" ::: "memory");
}
// fp32 bits fed directly: HW uses tf32 field, low 13 mantissa bits ignored (RZ).
__device__ __forceinline__ void mma_tf32(float* d, const uint32_t* a, const uint32_t* b) {
    asm volatile(
        "mma.sync.aligned.m16n8k8.row.col.f32.tf32.tf32.f32 "
        "{%0,%1,%2,%3}, {%4,%5,%6,%7}, {%8,%9}, {%0,%1,%2,%3};\n"
        : "+f"(d[0]), "+f"(d[1]), "+f"(d[2]), "+f"(d[3])
        : "r"(a[0]), "r"(a[1]), "r"(a[2]), "r"(a[3]), "r"(b[0]), "r"(b[1]));
}

// ============================================================================
// Prep: Wf transpose (raw f32 bits) — gives coalesced rows for fusion + bias.
// ============================================================================
__global__ void wf_transpose_kernel(const float* __restrict__ Wf) {
    __shared__ float t[32][33];
    int x = blockIdx.x * 32 + threadIdx.x;          // col f'
    int y0 = blockIdx.y * 32;                       // row h2
    for (int j = threadIdx.y; j < 32; j += 8)
        t[j][threadIdx.x] = Wf[(size_t)(y0 + j) * F + x];
    __syncthreads();
    int xo = blockIdx.y * 32 + threadIdx.x;         // WfT col = h2
    int yo = blockIdx.x * 32;                       // WfT row = f'
    for (int j = threadIdx.y; j < 32; j += 8)
        g_WfT[(size_t)(yo + j) * F + xo] = __float_as_uint(t[threadIdx.x][j]);
}

// ============================================================================
// Bias vectors, warp-per-output (1024 warps), coalesced.
//   biasU[f] = sum_h Wk[f,h] bq[h]
//   biasC[f] = bf[f] + sum_h bv[h] WfT[f][h] + (Sw bv[h] + bdr) WfT[f][256+h]
// ============================================================================
__global__ void k0_bias_kernel(const float* __restrict__ Wk, const float* __restrict__ bq,
                               const float* __restrict__ bv, const float* __restrict__ wdr,
                               const float* __restrict__ bdr_p, const float* __restrict__ bf)
{
    const int warp = (blockIdx.x * blockDim.x + threadIdx.x) >> 5;
    const int lane = threadIdx.x & 31;
    float s = 0.f;
    if (warp < F) {
        const int f = warp;
#pragma unroll
        for (int i = 0; i < H / 32; i++)
            s += Wk[(size_t)f * H + lane + 32 * i] * bq[lane + 32 * i];
#pragma unroll
        for (int o = 16; o > 0; o >>= 1) s += __shfl_xor_sync(~0u, s, o);
        if (lane == 0) g_biasU[f] = s;
    } else {
        const int f = warp - F;
        float Sw = 0.f;
#pragma unroll
        for (int k = 0; k < NL; k++) Sw += wdr[k];
        const float bdr = bdr_p[0];
#pragma unroll
        for (int i = 0; i < H / 32; i++) {
            int h = lane + 32 * i;
            float w0 = __uint_as_float(g_WfT[(size_t)f * F + h]);
            float w1 = __uint_as_float(g_WfT[(size_t)f * F + H + h]);
            s += bv[h] * w0 + (Sw * bv[h] + bdr) * w1;
        }
#pragma unroll
        for (int o = 16; o > 0; o >>= 1) s += __shfl_xor_sync(~0u, s, o);
        if (lane == 0) g_biasC[f] = bf[f] + s;
    }
}

// ============================================================================
// Core GEMM: C[m][n] = sum_k A[m][k] * B[n][k]  (A row-major, B = W^T rows).
// Block 128x128, warp tile 64x32, BK=32, 3-stage cp.async, 2 CTAs/SM.
// EPI 0: g_U[r*512+c] = acc + biasU[c]
// EPI 1: out[r*512+c] = relu(acc + biasC[c]) + resid[r*512+c]
// EPI 2: weight fusion (z batched): z0 Wu^T, z1 Wl^T, z2 Wg^T (x Sw), tf32 out.
// ============================================================================
template<int EPI>
__global__ void __launch_bounds__(TH, 2)
gemm_mma(const uint32_t* __restrict__ A, const uint32_t* __restrict__ A2,
         int splitChunk, int Astride,
         const uint32_t* __restrict__ Bmat, int Bstride, int Kchunks,
         void* __restrict__ outp, int outStride,
         const float* __restrict__ bias, const float* __restrict__ residp,
         const float* __restrict__ wdrp,
         const uint32_t* __restrict__ pWq, const uint32_t* __restrict__ pWk,
         const uint32_t* __restrict__ pWv)
{
    extern __shared__ uint32_t sm[];
    const uint32_t sb = s2u(sm);
    const int tid = threadIdx.x, warp = tid >> 5, lane = tid & 31;
    const int wm = (warp & 1) * 64, wn = (warp >> 1) * 32;
    const int bn = blockIdx.x * BN, bm = blockIdx.y * BM;

    int colOff = 0;
    float scale = 1.f;
    if (EPI == 2) {
        int z = blockIdx.z;
        if (z == 0) { A = pWk; Astride = H; Bmat = pWq;
                      outp = (void*)g_Wu; outStride = F; }
        else        { A = g_WfT + (z == 2 ? H : 0); Astride = F; Bmat = pWv;
                      outp = (void*)g_Wc; outStride = 2 * F;
                      colOff = (z == 2) ? F : 0; }
        Bstride = H; Kchunks = H / BK; splitChunk = 1 << 30;
        if (z == 2) {
            scale = 0.f;
#pragma unroll
            for (int k = 0; k < NL; k++) scale += wdrp[k];
        }
    }

    float acc[4][4][4];
#pragma unroll
    for (int i = 0; i < 4; i++)
#pragma unroll
        for (int j = 0; j < 4; j++)
#pragma unroll
            for (int v = 0; v < 4; v++) acc[i][j][v] = 0.f;

    auto issue_stage = [&](int c) {
        const int slot = c % STAGES;
        const uint32_t aBase = sb + slot * STAGE_BYTES;
        const uint32_t bBase = aBase + A_BYTES_ST;
        const uint32_t* Ap = A; int kloc = c * BK;
        if (c >= splitChunk) { Ap = A2; kloc = (c - splitChunk) * BK; }
#pragma unroll
        for (int j = 0; j < 4; j++) {                 // A: 1024 x 16B
            int i = tid + TH * j, m = i >> 3, cc = i & 7;
            cp16(aBase + m * 144 + cc * 16,
                 Ap + (size_t)(bm + m) * Astride + kloc + cc * 4);
        }
#pragma unroll
        for (int j = 0; j < 4; j++) {                 // B: 1024 x 16B
            int i = tid + TH * j, n = i >> 3, cc = i & 7;
            cp16(bBase + n * 144 + cc * 16,
                 Bmat + (size_t)(bn + n) * Bstride + c * BK + cc * 4);
        }
    };

    issue_stage(0); cp_commit();
    issue_stage(1); cp_commit();

    for (int c = 0; c < Kchunks; c++) {
        if (c + 2 < Kchunks) issue_stage(c + 2);
        cp_commit();
        cp_wait2();
        __syncthreads();

        const uint32_t* As = sm + (c % STAGES) * STAGE_WORDS;
        const uint32_t* Bs = As + A_WORDS;
#pragma unroll
        for (int kk = 0; kk < BK; kk += 8) {
            uint32_t af[4][4], bfr[4][2];
#pragma unroll
            for (int mf = 0; mf < 4; mf++) {
                int r0 = wm + mf * 16 + (lane >> 2);
                int c0 = kk + (lane & 3);
                af[mf][0] = As[r0 * 36 + c0];
                af[mf][1] = As[(r0 + 8) * 36 + c0];
                af[mf][2] = As[r0 * 36 + c0 + 4];
                af[mf][3] = As[(r0 + 8) * 36 + c0 + 4];
            }
#pragma unroll
            for (int nf = 0; nf < 4; nf++) {
                int n0 = wn + nf * 8 + (lane >> 2);
                int k0 = kk + (lane & 3);
                bfr[nf][0] = Bs[n0 * 36 + k0];
                bfr[nf][1] = Bs[n0 * 36 + k0 + 4];
            }
#pragma unroll
            for (int mf = 0; mf < 4; mf++)
#pragma unroll
                for (int nf = 0; nf < 4; nf++)
                    mma_tf32(acc[mf][nf], af[mf], bfr[nf]);
        }
        __syncthreads();
    }

    // ---- epilogue ----
#pragma unroll
    for (int mf = 0; mf < 4; mf++) {
        int r0 = bm + wm + mf * 16 + (lane >> 2);
#pragma unroll
        for (int nf = 0; nf < 4; nf++) {
            int c0 = bn + wn + nf * 8 + ((lane & 3) << 1);
#pragma unroll
            for (int half = 0; half < 2; half++) {
                int r = r0 + 8 * half;
                float d0 = acc[mf][nf][2 * half + 0];
                float d1 = acc[mf][nf][2 * half + 1];
                if (EPI == 0) {
                    float2 bu = *reinterpret_cast<const float2*>(bias + c0);
                    *reinterpret_cast<float2*>((float*)outp + (size_t)r * outStride + c0) =
                        make_float2(d0 + bu.x, d1 + bu.y);
                } else if (EPI == 1) {
                    float2 bc = *reinterpret_cast<const float2*>(bias + c0);
                    float2 rs = *reinterpret_cast<const float2*>(residp + (size_t)r * F + c0);
                    *reinterpret_cast<float2*>((float*)outp + (size_t)r * outStride + c0) =
                        make_float2(fmaxf(d0 + bc.x, 0.f) + rs.x,
                                    fmaxf(d1 + bc.y, 0.f) + rs.y);
                } else {
                    *reinterpret_cast<uint2*>((uint32_t*)outp +
                        (size_t)r * outStride + colOff + c0) =
                        make_uint2(f2tf(d0 * scale), f2tf(d1 * scale));
                }
            }
        }
    }
}

// ============================================================================
// K2: per-row attention over 12 local tokens (HBM-bound streaming pass).
// ============================================================================
__global__ void k2_attn_kernel(const float* __restrict__ gfeat,
                               const float* __restrict__ lfeat,
                               const float* __restrict__ wdr,
                               const float* __restrict__ bdr_p)
{
    const int b = blockIdx.x;
    const int t = threadIdx.x;     // 128
    const int f0 = t * 4;
    const float* lb = lfeat + (size_t)b * NL * F;

    float4 u4 = *reinterpret_cast<const float4*>(&g_U[(size_t)b * F + f0]);

    float4 loc[NL];
    float part[NL];
#pragma unroll
    for (int k = 0; k < NL; k++) {
        loc[k] = *reinterpret_cast<const float4*>(&lb[k * F + f0]);
        part[k] = loc[k].x * u4.x + loc[k].y * u4.y + loc[k].z * u4.z + loc[k].w * u4.w;
    }
#pragma unroll
    for (int k = 0; k < NL; k++) {
#pragma unroll
        for (int o = 16; o > 0; o >>= 1)
            part[k] += __shfl_xor_sync(0xffffffffu, part[k], o);
    }
    __shared__ float red[4][NL];
    const int lane = t & 31, w = t >> 5;
    if (lane == 0) {
#pragma unroll
        for (int k = 0; k < NL; k++) red[w][k] = part[k];
    }
    __syncthreads();

    float a2[NL];
    float m = -1e30f;
#pragma unroll
    for (int k = 0; k < NL; k++) {
        a2[k] = (red[0][k] + red[1][k] + red[2][k] + red[3][k]) * 0.0625f; // 1/sqrt(256)
        m = fmaxf(m, a2[k]);
    }
    float s = 0.f;
#pragma unroll
    for (int k = 0; k < NL; k++) { a2[k] = __expf(a2[k] - m); s += a2[k]; }
    const float inv = 1.f / s;

    float4 pool = make_float4(0.f, 0.f, 0.f, 0.f);
    float4 lfm  = make_float4(0.f, 0.f, 0.f, 0.f);
#pragma unroll
    for (int k = 0; k < NL; k++) {
        float a  = a2[k] * inv;
        float wd = wdr[k];
        pool.x += a * loc[k].x;  pool.y += a * loc[k].y;
        pool.z += a * loc[k].z;  pool.w += a * loc[k].w;
        lfm.x  += wd * loc[k].x; lfm.y  += wd * loc[k].y;
        lfm.z  += wd * loc[k].z; lfm.w  += wd * loc[k].w;
    }
    float4 g4 = *reinterpret_cast<const float4*>(&gfeat[(size_t)b * F + f0]);
    const float bdr = bdr_p[0];
    *reinterpret_cast<float4*>(&g_pooled[(size_t)b * F + f0]) = pool;
    *reinterpret_cast<float4*>(&g_resid[(size_t)b * F + f0]) =
        make_float4(lfm.x + bdr + g4.x, lfm.y + bdr + g4.y,
                    lfm.z + bdr + g4.z, lfm.w + bdr + g4.w);
}

// ============================================================================
extern "C" void kernel_launch(void* const* d_in, const int* in_sizes, int n_in,
                              void* d_out, int out_size)
{
    const float* gfeat = (const float*)d_in[0];
    const float* lfeat = (const float*)d_in[1];
    const float* Wq    = (const float*)d_in[2];
    const float* bq    = (const float*)d_in[3];
    const float* Wk    = (const float*)d_in[4];
    // d_in[5] (bk) cancels in the length-12 softmax.
    const float* Wv    = (const float*)d_in[6];
    const float* bv    = (const float*)d_in[7];
    const float* wdr   = (const float*)d_in[8];
    const float* bdr   = (const float*)d_in[9];
    const float* Wf    = (const float*)d_in[10];
    const float* bf    = (const float*)d_in[11];
    float* out = (float*)d_out;

    const int B = in_sizes[0] / F;   // 16384

    cudaFuncSetAttribute(gemm_mma<0>, cudaFuncAttributeMaxDynamicSharedMemorySize, SMEM_SZ);
    cudaFuncSetAttribute(gemm_mma<1>, cudaFuncAttributeMaxDynamicSharedMemorySize, SMEM_SZ);
    cudaFuncSetAttribute(gemm_mma<2>, cudaFuncAttributeMaxDynamicSharedMemorySize, SMEM_SZ);

    uint32_t* pWu  = nullptr; cudaGetSymbolAddress((void**)&pWu,  g_Wu);
    uint32_t* pWc  = nullptr; cudaGetSymbolAddress((void**)&pWc,  g_Wc);
    float*    pPool= nullptr; cudaGetSymbolAddress((void**)&pPool,g_pooled);
    float*    pU   = nullptr; cudaGetSymbolAddress((void**)&pU,   g_U);
    float*    pRes = nullptr; cudaGetSymbolAddress((void**)&pRes, g_resid);
    float*    pBU  = nullptr; cudaGetSymbolAddress((void**)&pBU,  g_biasU);
    float*    pBC  = nullptr; cudaGetSymbolAddress((void**)&pBC,  g_biasC);

    // --- prep (fp32 bits feed tf32 MMA directly; only Wf needs a transpose) ---
    wf_transpose_kernel<<<dim3(16, 16), dim3(32, 8)>>>(Wf);
    k0_bias_kernel<<<128, 256>>>(Wk, bq, bv, wdr, bdr, bf);

    // weight fusion: z=0 Wu^T, z=1 Wl^T, z=2 Wg^T (scaled by Sw)
    gemm_mma<2><<<dim3(F / BN, F / BM, 3), TH, SMEM_SZ>>>(
        nullptr, nullptr, 0, 0, nullptr, 0, 0, nullptr, 0,
        nullptr, nullptr, wdr,
        (const uint32_t*)Wq, (const uint32_t*)Wk, (const uint32_t*)Wv);

    // GEMM1: U = gfeat @ Wu + b_u   (K=512 -> 16 chunks)
    gemm_mma<0><<<dim3(F / BN, B / BM), TH, SMEM_SZ>>>(
        (const uint32_t*)gfeat, (const uint32_t*)gfeat, 1 << 30, F, pWu, F, F / BK,
        pU, F, pBU, nullptr, nullptr, nullptr, nullptr, nullptr);

    // K2: softmax over 12 locals -> pooled + resid
    k2_attn_kernel<<<B, 128>>>(gfeat, lfeat, wdr, bdr);

    // GEMM2: out = relu([pooled|gfeat] @ Wc + c) + resid  (K=1024 -> 32 chunks)
    gemm_mma<1><<<dim3(F / BN, B / BM), TH, SMEM_SZ>>>(
        (const uint32_t*)pPool, (const uint32_t*)gfeat, F / BK, F, pWc, 2 * F, 2 * F / BK,
        out, F, pBC, pRes, nullptr, nullptr, nullptr, nullptr);
}

// round 11
// speedup vs baseline: 1.8386x; 1.1235x over previous
#include <cuda_runtime.h>
#include <cstdint>

// ============================================================================
// ESF_78391743086936 — algebraic restructure + legacy mma.sync TF32 GEMMs.
//   u      = global @ Wu + b_u ;  Wu = Wq Wk^T, b_u = Wk bq   (bk cancels)
//   a2     = softmax_k( (local_k . u) / 16 )
//   pooled = sum_k a2[k] local[k]
//   out    = relu( [pooled|global] @ [Wl;Wg] + c ) + lf_mean + b_dr + global
//   Wl = Wv Wf[:H], Wg = Sw * Wv Wf[H:], c = folded biases, Sw = sum w_dr
// R11: ldmatrix fragment loads (SW128-swizzled smem), single-sync 3-stage
// cp.async pipeline, 2 CTAs/SM.
// ============================================================================

constexpr int F  = 512;
constexpr int H  = 256;
constexpr int NL = 12;
constexpr int MAXB = 16384;

// GEMM tiling: block 128x128, 8 warps (2m x 4n), warp tile 64x32, BK=32.
constexpr int BM = 128, BN = 128, BK = 32, TH = 256, STAGES = 3;
constexpr int A_BYTES_ST = BM * BK * 4;              // 16384 (128B rows, swizzled)
constexpr int STAGE_BYTES = 2 * A_BYTES_ST;          // 32768
constexpr int SMEM_SZ = STAGES * STAGE_BYTES;        // 98304 -> 2 CTAs/SM

// ---- device scratch ----
__device__ float    g_pooled[(size_t)MAXB * F];
__device__ float    g_U  [(size_t)MAXB * F];    // u = g@Wu + b_u
__device__ float    g_resid[(size_t)MAXB * F];  // lf_mean + b_dr + global
__device__ uint32_t g_Wu [F * F];               // [n=f'][k=f] (Wu^T) tf32
__device__ uint32_t g_Wc [F * 2 * F];           // [n=f'][0:512 Wl^T | 512:1024 Wg^T]
__device__ uint32_t g_WfT[F * F];               // WfT[f'][h2] = Wf[h2][f'] raw f32 bits
__device__ float    g_biasU[F], g_biasC[F];

// ---------------- helpers ----------------
__device__ __forceinline__ uint32_t f2tf(float x) {
    uint32_t u; asm("cvt.rna.tf32.f32 %0, %1;" : "=r"(u) : "f"(x)); return u;
}
__device__ __forceinline__ uint32_t s2u(const void* p) {
    uint32_t a;
    asm("{ .reg .u64 t; cvta.to.shared.u64 t, %1; cvt.u32.u64 %0, t; }"
        : "=r"(a) : "l"(p));
    return a;
}
__device__ __forceinline__ uint32_t swz(uint32_t b) { return b ^ ((b >> 3) & 0x70); }
__device__ __forceinline__ void cp16(uint32_t dst, const void* src) {
    asm volatile("cp.async.cg.shared.global [%0], [%1], 16;"
                 :: "r"(dst), "l"(src) : "memory");
}
__device__ __forceinline__ void cp_commit() {
    asm volatile("cp.async.commit_group;" ::: "memory");
}
__device__ __forceinline__ void cp_wait1() {
    asm volatile("cp.async.wait_group 1;" ::: "memory");
}
__device__ __forceinline__ void ldsm4(uint32_t* r, uint32_t addr) {
    asm volatile("ldmatrix.sync.aligned.m8n8.x4.shared.b16 {%0,%1,%2,%3}, [%4];"
                 : "=r"(r[0]), "=r"(r[1]), "=r"(r[2]), "=r"(r[3]) : "r"(addr));
}
// fp32 bits fed directly: HW uses tf32 field, low mantissa bits ignored (RZ).
__device__ __forceinline__ void mma_tf32(float* d, const uint32_t* a, const uint32_t* b) {
    asm volatile(
        "mma.sync.aligned.m16n8k8.row.col.f32.tf32.tf32.f32 "
        "{%0,%1,%2,%3}, {%4,%5,%6,%7}, {%8,%9}, {%0,%1,%2,%3};\n"
        : "+f"(d[0]), "+f"(d[1]), "+f"(d[2]), "+f"(d[3])
        : "r"(a[0]), "r"(a[1]), "r"(a[2]), "r"(a[3]), "r"(b[0]), "r"(b[1]));
}

// ============================================================================
// Prep: Wf transpose (raw f32 bits) — coalesced rows for fusion + bias.
// ============================================================================
__global__ void wf_transpose_kernel(const float* __restrict__ Wf) {
    __shared__ float t[32][33];
    int x = blockIdx.x * 32 + threadIdx.x;          // col f'
    int y0 = blockIdx.y * 32;                       // row h2
    for (int j = threadIdx.y; j < 32; j += 8)
        t[j][threadIdx.x] = Wf[(size_t)(y0 + j) * F + x];
    __syncthreads();
    int xo = blockIdx.y * 32 + threadIdx.x;         // WfT col = h2
    int yo = blockIdx.x * 32;                       // WfT row = f'
    for (int j = threadIdx.y; j < 32; j += 8)
        g_WfT[(size_t)(yo + j) * F + xo] = __float_as_uint(t[threadIdx.x][j]);
}

// ============================================================================
// Bias vectors, warp-per-output (1024 warps), coalesced.
// ============================================================================
__global__ void k0_bias_kernel(const float* __restrict__ Wk, const float* __restrict__ bq,
                               const float* __restrict__ bv, const float* __restrict__ wdr,
                               const float* __restrict__ bdr_p, const float* __restrict__ bf)
{
    const int warp = (blockIdx.x * blockDim.x + threadIdx.x) >> 5;
    const int lane = threadIdx.x & 31;
    float s = 0.f;
    if (warp < F) {
        const int f = warp;
#pragma unroll
        for (int i = 0; i < H / 32; i++)
            s += Wk[(size_t)f * H + lane + 32 * i] * bq[lane + 32 * i];
#pragma unroll
        for (int o = 16; o > 0; o >>= 1) s += __shfl_xor_sync(~0u, s, o);
        if (lane == 0) g_biasU[f] = s;
    } else {
        const int f = warp - F;
        float Sw = 0.f;
#pragma unroll
        for (int k = 0; k < NL; k++) Sw += wdr[k];
        const float bdr = bdr_p[0];
#pragma unroll
        for (int i = 0; i < H / 32; i++) {
            int h = lane + 32 * i;
            float w0 = __uint_as_float(g_WfT[(size_t)f * F + h]);
            float w1 = __uint_as_float(g_WfT[(size_t)f * F + H + h]);
            s += bv[h] * w0 + (Sw * bv[h] + bdr) * w1;
        }
#pragma unroll
        for (int o = 16; o > 0; o >>= 1) s += __shfl_xor_sync(~0u, s, o);
        if (lane == 0) g_biasC[f] = bf[f] + s;
    }
}

// ============================================================================
// Core GEMM: C[m][n] = sum_k A[m][k] * B[n][k]  (A row-major, B = W^T rows).
// Block 128x128, warp tile 64x32, BK=32, ldmatrix frags, 1 sync/chunk.
// EPI 0: g_U = acc + biasU ; EPI 1: out = relu(acc+biasC)+resid ;
// EPI 2: weight fusion (z): z0 Wu^T, z1 Wl^T, z2 Wg^T (x Sw), tf32 bits out.
// ============================================================================
template<int EPI>
__global__ void __launch_bounds__(TH, 2)
gemm_mma(const uint32_t* __restrict__ A, const uint32_t* __restrict__ A2,
         int splitChunk, int Astride,
         const uint32_t* __restrict__ Bmat, int Bstride, int Kchunks,
         void* __restrict__ outp, int outStride,
         const float* __restrict__ bias, const float* __restrict__ residp,
         const float* __restrict__ wdrp,
         const uint32_t* __restrict__ pWq, const uint32_t* __restrict__ pWk,
         const uint32_t* __restrict__ pWv)
{
    extern __shared__ uint32_t sm[];
    const uint32_t sb = s2u(sm);
    const int tid = threadIdx.x, warp = tid >> 5, lane = tid & 31;
    const int wm = (warp & 1) * 64, wn = (warp >> 1) * 32;
    const int bn = blockIdx.x * BN, bm = blockIdx.y * BM;

    int colOff = 0;
    float scale = 1.f;
    if (EPI == 2) {
        int z = blockIdx.z;
        if (z == 0) { A = pWk; Astride = H; Bmat = pWq;
                      outp = (void*)g_Wu; outStride = F; }
        else        { A = g_WfT + (z == 2 ? H : 0); Astride = F; Bmat = pWv;
                      outp = (void*)g_Wc; outStride = 2 * F;
                      colOff = (z == 2) ? F : 0; }
        Bstride = H; Kchunks = H / BK; splitChunk = 1 << 30;
        if (z == 2) {
            scale = 0.f;
#pragma unroll
            for (int k = 0; k < NL; k++) scale += wdrp[k];
        }
    }

    float acc[4][4][4];
#pragma unroll
    for (int i = 0; i < 4; i++)
#pragma unroll
        for (int j = 0; j < 4; j++)
#pragma unroll
            for (int v = 0; v < 4; v++) acc[i][j][v] = 0.f;

    // ldmatrix per-thread address components (byte offsets within tile)
    const int g8 = lane >> 3, rin = lane & 7;
    const int aRow = wm + ((g8 & 1) << 3) + rin;     // + mf*16
    const int aCoff = (g8 >> 1) << 4;                // 0 or 16
    const int bRow = wn + ((g8 >> 1) << 3) + rin;    // + nfp*16
    const int bCoff = (g8 & 1) << 4;

    auto issue_stage = [&](int c) {
        const int slot = c % STAGES;
        const uint32_t aBase = sb + slot * STAGE_BYTES;
        const uint32_t bBase = aBase + A_BYTES_ST;
        const uint32_t* Ap = A; int kloc = c * BK;
        if (c >= splitChunk) { Ap = A2; kloc = (c - splitChunk) * BK; }
#pragma unroll
        for (int j = 0; j < 4; j++) {                 // A: 1024 x 16B
            int i = tid + TH * j, m = i >> 3, cc = i & 7;
            cp16(aBase + swz(m * 128 + cc * 16),
                 Ap + (size_t)(bm + m) * Astride + kloc + cc * 4);
        }
#pragma unroll
        for (int j = 0; j < 4; j++) {                 // B: 1024 x 16B
            int i = tid + TH * j, n = i >> 3, cc = i & 7;
            cp16(bBase + swz(n * 128 + cc * 16),
                 Bmat + (size_t)(bn + n) * Bstride + c * BK + cc * 4);
        }
    };

    issue_stage(0); cp_commit();
    issue_stage(1); cp_commit();

    for (int c = 0; c < Kchunks; c++) {
        cp_wait1();          // stage c arrived (groups G0..Gc done)
        __syncthreads();     // publish stage c; all warps past compute(c-1)
        if (c + 2 < Kchunks) issue_stage(c + 2);
        cp_commit();         // keep group accounting (possibly empty)

        const uint32_t aBase = sb + (c % STAGES) * STAGE_BYTES;
        const uint32_t bBase = aBase + A_BYTES_ST;
#pragma unroll
        for (int kk = 0; kk < BK; kk += 8) {
            uint32_t af[4][4], bfr[4][2];
#pragma unroll
            for (int mf = 0; mf < 4; mf++)
                ldsm4(af[mf], aBase + swz((aRow + mf * 16) * 128 + kk * 4 + aCoff));
#pragma unroll
            for (int nfp = 0; nfp < 2; nfp++) {
                uint32_t r[4];
                ldsm4(r, bBase + swz((bRow + nfp * 16) * 128 + kk * 4 + bCoff));
                bfr[2 * nfp][0] = r[0]; bfr[2 * nfp][1] = r[1];
                bfr[2 * nfp + 1][0] = r[2]; bfr[2 * nfp + 1][1] = r[3];
            }
#pragma unroll
            for (int mf = 0; mf < 4; mf++)
#pragma unroll
                for (int nf = 0; nf < 4; nf++)
                    mma_tf32(acc[mf][nf], af[mf], bfr[nf]);
        }
    }

    // ---- epilogue ----
#pragma unroll
    for (int mf = 0; mf < 4; mf++) {
        int r0 = bm + wm + mf * 16 + (lane >> 2);
#pragma unroll
        for (int nf = 0; nf < 4; nf++) {
            int c0 = bn + wn + nf * 8 + ((lane & 3) << 1);
#pragma unroll
            for (int half = 0; half < 2; half++) {
                int r = r0 + 8 * half;
                float d0 = acc[mf][nf][2 * half + 0];
                float d1 = acc[mf][nf][2 * half + 1];
                if (EPI == 0) {
                    float2 bu = *reinterpret_cast<const float2*>(bias + c0);
                    *reinterpret_cast<float2*>((float*)outp + (size_t)r * outStride + c0) =
                        make_float2(d0 + bu.x, d1 + bu.y);
                } else if (EPI == 1) {
                    float2 bc = *reinterpret_cast<const float2*>(bias + c0);
                    float2 rs = *reinterpret_cast<const float2*>(residp + (size_t)r * F + c0);
                    *reinterpret_cast<float2*>((float*)outp + (size_t)r * outStride + c0) =
                        make_float2(fmaxf(d0 + bc.x, 0.f) + rs.x,
                                    fmaxf(d1 + bc.y, 0.f) + rs.y);
                } else {
                    *reinterpret_cast<uint2*>((uint32_t*)outp +
                        (size_t)r * outStride + colOff + c0) =
                        make_uint2(f2tf(d0 * scale), f2tf(d1 * scale));
                }
            }
        }
    }
}

// ============================================================================
// K2: per-row attention over 12 local tokens (HBM-bound streaming pass).
// ============================================================================
__global__ void k2_attn_kernel(const float* __restrict__ gfeat,
                               const float* __restrict__ lfeat,
                               const float* __restrict__ wdr,
                               const float* __restrict__ bdr_p)
{
    const int b = blockIdx.x;
    const int t = threadIdx.x;     // 128
    const int f0 = t * 4;
    const float* lb = lfeat + (size_t)b * NL * F;

    float4 u4 = *reinterpret_cast<const float4*>(&g_U[(size_t)b * F + f0]);

    float4 loc[NL];
    float part[NL];
#pragma unroll
    for (int k = 0; k < NL; k++) {
        loc[k] = *reinterpret_cast<const float4*>(&lb[k * F + f0]);
        part[k] = loc[k].x * u4.x + loc[k].y * u4.y + loc[k].z * u4.z + loc[k].w * u4.w;
    }
#pragma unroll
    for (int k = 0; k < NL; k++) {
#pragma unroll
        for (int o = 16; o > 0; o >>= 1)
            part[k] += __shfl_xor_sync(0xffffffffu, part[k], o);
    }
    __shared__ float red[4][NL];
    const int lane = t & 31, w = t >> 5;
    if (lane == 0) {
#pragma unroll
        for (int k = 0; k < NL; k++) red[w][k] = part[k];
    }
    __syncthreads();

    float a2[NL];
    float m = -1e30f;
#pragma unroll
    for (int k = 0; k < NL; k++) {
        a2[k] = (red[0][k] + red[1][k] + red[2][k] + red[3][k]) * 0.0625f; // 1/sqrt(256)
        m = fmaxf(m, a2[k]);
    }
    float s = 0.f;
#pragma unroll
    for (int k = 0; k < NL; k++) { a2[k] = __expf(a2[k] - m); s += a2[k]; }
    const float inv = 1.f / s;

    float4 pool = make_float4(0.f, 0.f, 0.f, 0.f);
    float4 lfm  = make_float4(0.f, 0.f, 0.f, 0.f);
#pragma unroll
    for (int k = 0; k < NL; k++) {
        float a  = a2[k] * inv;
        float wd = wdr[k];
        pool.x += a * loc[k].x;  pool.y += a * loc[k].y;
        pool.z += a * loc[k].z;  pool.w += a * loc[k].w;
        lfm.x  += wd * loc[k].x; lfm.y  += wd * loc[k].y;
        lfm.z  += wd * loc[k].z; lfm.w  += wd * loc[k].w;
    }
    float4 g4 = *reinterpret_cast<const float4*>(&gfeat[(size_t)b * F + f0]);
    const float bdr = bdr_p[0];
    *reinterpret_cast<float4*>(&g_pooled[(size_t)b * F + f0]) = pool;
    *reinterpret_cast<float4*>(&g_resid[(size_t)b * F + f0]) =
        make_float4(lfm.x + bdr + g4.x, lfm.y + bdr + g4.y,
                    lfm.z + bdr + g4.z, lfm.w + bdr + g4.w);
}

// ============================================================================
extern "C" void kernel_launch(void* const* d_in, const int* in_sizes, int n_in,
                              void* d_out, int out_size)
{
    const float* gfeat = (const float*)d_in[0];
    const float* lfeat = (const float*)d_in[1];
    const float* Wq    = (const float*)d_in[2];
    const float* bq    = (const float*)d_in[3];
    const float* Wk    = (const float*)d_in[4];
    // d_in[5] (bk) cancels in the length-12 softmax.
    const float* Wv    = (const float*)d_in[6];
    const float* bv    = (const float*)d_in[7];
    const float* wdr   = (const float*)d_in[8];
    const float* bdr   = (const float*)d_in[9];
    const float* Wf    = (const float*)d_in[10];
    const float* bf    = (const float*)d_in[11];
    float* out = (float*)d_out;

    const int B = in_sizes[0] / F;   // 16384

    cudaFuncSetAttribute(gemm_mma<0>, cudaFuncAttributeMaxDynamicSharedMemorySize, SMEM_SZ);
    cudaFuncSetAttribute(gemm_mma<1>, cudaFuncAttributeMaxDynamicSharedMemorySize, SMEM_SZ);
    cudaFuncSetAttribute(gemm_mma<2>, cudaFuncAttributeMaxDynamicSharedMemorySize, SMEM_SZ);

    uint32_t* pWu  = nullptr; cudaGetSymbolAddress((void**)&pWu,  g_Wu);
    uint32_t* pWc  = nullptr; cudaGetSymbolAddress((void**)&pWc,  g_Wc);
    float*    pPool= nullptr; cudaGetSymbolAddress((void**)&pPool,g_pooled);
    float*    pU   = nullptr; cudaGetSymbolAddress((void**)&pU,   g_U);
    float*    pRes = nullptr; cudaGetSymbolAddress((void**)&pRes, g_resid);
    float*    pBU  = nullptr; cudaGetSymbolAddress((void**)&pBU,  g_biasU);
    float*    pBC  = nullptr; cudaGetSymbolAddress((void**)&pBC,  g_biasC);

    // --- prep (fp32 bits feed tf32 MMA directly; only Wf needs a transpose) ---
    wf_transpose_kernel<<<dim3(16, 16), dim3(32, 8)>>>(Wf);
    k0_bias_kernel<<<128, 256>>>(Wk, bq, bv, wdr, bdr, bf);

    // weight fusion: z=0 Wu^T, z=1 Wl^T, z=2 Wg^T (scaled by Sw)
    gemm_mma<2><<<dim3(F / BN, F / BM, 3), TH, SMEM_SZ>>>(
        nullptr, nullptr, 0, 0, nullptr, 0, 0, nullptr, 0,
        nullptr, nullptr, wdr,
        (const uint32_t*)Wq, (const uint32_t*)Wk, (const uint32_t*)Wv);

    // GEMM1: U = gfeat @ Wu + b_u   (K=512 -> 16 chunks)
    gemm_mma<0><<<dim3(F / BN, B / BM), TH, SMEM_SZ>>>(
        (const uint32_t*)gfeat, (const uint32_t*)gfeat, 1 << 30, F, pWu, F, F / BK,
        pU, F, pBU, nullptr, nullptr, nullptr, nullptr, nullptr);

    // K2: softmax over 12 locals -> pooled + resid
    k2_attn_kernel<<<B, 128>>>(gfeat, lfeat, wdr, bdr);

    // GEMM2: out = relu([pooled|gfeat] @ Wc + c) + resid  (K=1024 -> 32 chunks)
    gemm_mma<1><<<dim3(F / BN, B / BM), TH, SMEM_SZ>>>(
        (const uint32_t*)pPool, (const uint32_t*)gfeat, F / BK, F, pWc, 2 * F, 2 * F / BK,
        out, F, pBC, pRes, nullptr, nullptr, nullptr, nullptr);
}

// round 13
// speedup vs baseline: 1.8945x; 1.0304x over previous
#include <cuda_runtime.h>
#include <cstdint>

// ============================================================================
// ESF_78391743086936 — algebraic restructure + legacy mma.sync TF32 GEMMs.
//   u      = global @ Wu + b_u ;  Wu = Wq Wk^T, b_u = Wk bq   (bk cancels)
//   a2     = softmax_k( (local_k . u) / 16 )
//   pooled = sum_k a2[k] local[k]
//   out    = relu( [pooled|global] @ [Wl;Wg] + c ) + lf_mean + b_dr + global
//   Wl = Wv Wf[:H], Wg = Sw * Wv Wf[H:], c = folded biases, Sw = sum w_dr
// R13: R12's double-buffered ldmatrix fragment pipeline with the hoisted
// swizzle offsets fixed: swz(x+d) == swz(x) ^ d for d in {32,64,96}
// (d touches only bits 5-6; XOR, never ADD, after the swizzle).
// ============================================================================

constexpr int F  = 512;
constexpr int H  = 256;
constexpr int NL = 12;
constexpr int MAXB = 16384;

// GEMM tiling: block 128x128, 8 warps (2m x 4n), warp tile 64x32, BK=32.
constexpr int BM = 128, BN = 128, BK = 32, TH = 256, STAGES = 3;
constexpr int A_BYTES_ST = BM * BK * 4;              // 16384 (128B rows, swizzled)
constexpr int STAGE_BYTES = 2 * A_BYTES_ST;          // 32768
constexpr int SMEM_SZ = STAGES * STAGE_BYTES;        // 98304 -> 2 CTAs/SM

// ---- device scratch ----
__device__ float    g_pooled[(size_t)MAXB * F];
__device__ float    g_U  [(size_t)MAXB * F];    // u = g@Wu + b_u
__device__ float    g_resid[(size_t)MAXB * F];  // lf_mean + b_dr + global
__device__ uint32_t g_Wu [F * F];               // [n=f'][k=f] (Wu^T) tf32
__device__ uint32_t g_Wc [F * 2 * F];           // [n=f'][0:512 Wl^T | 512:1024 Wg^T]
__device__ uint32_t g_WfT[F * F];               // WfT[f'][h2] = Wf[h2][f'] raw f32 bits
__device__ float    g_biasU[F], g_biasC[F];

// ---------------- helpers ----------------
__device__ __forceinline__ uint32_t f2tf(float x) {
    uint32_t u; asm("cvt.rna.tf32.f32 %0, %1;" : "=r"(u) : "f"(x)); return u;
}
__device__ __forceinline__ uint32_t s2u(const void* p) {
    uint32_t a;
    asm("{ .reg .u64 t; cvta.to.shared.u64 t, %1; cvt.u32.u64 %0, t; }"
        : "=r"(a) : "l"(p));
    return a;
}
__device__ __forceinline__ uint32_t swz(uint32_t b) { return b ^ ((b >> 3) & 0x70); }
__device__ __forceinline__ void cp16(uint32_t dst, const void* src) {
    asm volatile("cp.async.cg.shared.global [%0], [%1], 16;"
                 :: "r"(dst), "l"(src) : "memory");
}
__device__ __forceinline__ void cp_commit() {
    asm volatile("cp.async.commit_group;" ::: "memory");
}
__device__ __forceinline__ void cp_wait1() {
    asm volatile("cp.async.wait_group 1;" ::: "memory");
}
__device__ __forceinline__ void ldsm4(uint32_t* r, uint32_t addr) {
    asm volatile("ldmatrix.sync.aligned.m8n8.x4.shared.b16 {%0,%1,%2,%3}, [%4];"
                 : "=r"(r[0]), "=r"(r[1]), "=r"(r[2]), "=r"(r[3]) : "r"(addr));
}
// fp32 bits fed directly: HW uses tf32 field, low mantissa bits ignored (RZ).
__device__ __forceinline__ void mma_tf32(float* d, const uint32_t* a, const uint32_t* b) {
    asm volatile(
        "mma.sync.aligned.m16n8k8.row.col.f32.tf32.tf32.f32 "
        "{%0,%1,%2,%3}, {%4,%5,%6,%7}, {%8,%9}, {%0,%1,%2,%3};\n"
        : "+f"(d[0]), "+f"(d[1]), "+f"(d[2]), "+f"(d[3])
        : "r"(a[0]), "r"(a[1]), "r"(a[2]), "r"(a[3]), "r"(b[0]), "r"(b[1]));
}

// ============================================================================
// Prep: Wf transpose (raw f32 bits) — coalesced rows for fusion + bias.
// ============================================================================
__global__ void wf_transpose_kernel(const float* __restrict__ Wf) {
    __shared__ float t[32][33];
    int x = blockIdx.x * 32 + threadIdx.x;          // col f'
    int y0 = blockIdx.y * 32;                       // row h2
    for (int j = threadIdx.y; j < 32; j += 8)
        t[j][threadIdx.x] = Wf[(size_t)(y0 + j) * F + x];
    __syncthreads();
    int xo = blockIdx.y * 32 + threadIdx.x;         // WfT col = h2
    int yo = blockIdx.x * 32;                       // WfT row = f'
    for (int j = threadIdx.y; j < 32; j += 8)
        g_WfT[(size_t)(yo + j) * F + xo] = __float_as_uint(t[threadIdx.x][j]);
}

// ============================================================================
// Bias vectors, warp-per-output (1024 warps), coalesced.
// ============================================================================
__global__ void k0_bias_kernel(const float* __restrict__ Wk, const float* __restrict__ bq,
                               const float* __restrict__ bv, const float* __restrict__ wdr,
                               const float* __restrict__ bdr_p, const float* __restrict__ bf)
{
    const int warp = (blockIdx.x * blockDim.x + threadIdx.x) >> 5;
    const int lane = threadIdx.x & 31;
    float s = 0.f;
    if (warp < F) {
        const int f = warp;
#pragma unroll
        for (int i = 0; i < H / 32; i++)
            s += Wk[(size_t)f * H + lane + 32 * i] * bq[lane + 32 * i];
#pragma unroll
        for (int o = 16; o > 0; o >>= 1) s += __shfl_xor_sync(~0u, s, o);
        if (lane == 0) g_biasU[f] = s;
    } else {
        const int f = warp - F;
        float Sw = 0.f;
#pragma unroll
        for (int k = 0; k < NL; k++) Sw += wdr[k];
        const float bdr = bdr_p[0];
#pragma unroll
        for (int i = 0; i < H / 32; i++) {
            int h = lane + 32 * i;
            float w0 = __uint_as_float(g_WfT[(size_t)f * F + h]);
            float w1 = __uint_as_float(g_WfT[(size_t)f * F + H + h]);
            s += bv[h] * w0 + (Sw * bv[h] + bdr) * w1;
        }
#pragma unroll
        for (int o = 16; o > 0; o >>= 1) s += __shfl_xor_sync(~0u, s, o);
        if (lane == 0) g_biasC[f] = bf[f] + s;
    }
}

// ============================================================================
// Core GEMM: C[m][n] = sum_k A[m][k] * B[n][k]  (A row-major, B = W^T rows).
// Block 128x128, warp tile 64x32, BK=32, ldmatrix double-buffered frags,
// 1 sync/chunk, 3-stage cp.async.
// EPI 0: g_U = acc + biasU ; EPI 1: out = relu(acc+biasC)+resid ;
// EPI 2: weight fusion (z): z0 Wu^T, z1 Wl^T, z2 Wg^T (x Sw), tf32 bits out.
// ============================================================================
template<int EPI>
__global__ void __launch_bounds__(TH, 2)
gemm_mma(const uint32_t* __restrict__ A, const uint32_t* __restrict__ A2,
         int splitChunk, int Astride,
         const uint32_t* __restrict__ Bmat, int Bstride, int Kchunks,
         void* __restrict__ outp, int outStride,
         const float* __restrict__ bias, const float* __restrict__ residp,
         const float* __restrict__ wdrp,
         const uint32_t* __restrict__ pWq, const uint32_t* __restrict__ pWk,
         const uint32_t* __restrict__ pWv)
{
    extern __shared__ uint32_t sm[];
    const uint32_t sb = s2u(sm);
    const int tid = threadIdx.x, warp = tid >> 5, lane = tid & 31;
    const int wm = (warp & 1) * 64, wn = (warp >> 1) * 32;
    const int bn = blockIdx.x * BN, bm = blockIdx.y * BM;

    int colOff = 0;
    float scale = 1.f;
    if (EPI == 2) {
        int z = blockIdx.z;
        if (z == 0) { A = pWk; Astride = H; Bmat = pWq;
                      outp = (void*)g_Wu; outStride = F; }
        else        { A = g_WfT + (z == 2 ? H : 0); Astride = F; Bmat = pWv;
                      outp = (void*)g_Wc; outStride = 2 * F;
                      colOff = (z == 2) ? F : 0; }
        Bstride = H; Kchunks = H / BK; splitChunk = 1 << 30;
        if (z == 2) {
            scale = 0.f;
#pragma unroll
            for (int k = 0; k < NL; k++) scale += wdrp[k];
        }
    }

    float acc[4][4][4];
#pragma unroll
    for (int i = 0; i < 4; i++)
#pragma unroll
        for (int j = 0; j < 4; j++)
#pragma unroll
            for (int v = 0; v < 4; v++) acc[i][j][v] = 0.f;

    // ldmatrix per-thread swizzled base offsets.
    // kk advance: pre-swizzle col = coff(bit4) + kk*4(bits 5-6) are disjoint
    // bit fields and the swizzle mask depends only on row bits, so
    // swz(base + d) == swz(base) ^ d for d in {0,32,64,96}.  (R12 used '+',
    // which carries out of bit 6 into the row field -> OOB. XOR is exact.)
    const int g8 = lane >> 3, rin = lane & 7;
    const int aRow = ((g8 & 1) << 3) + rin;          // + wm + mf*16
    const int aCoff = (g8 >> 1) << 4;
    const int bRow = ((g8 >> 1) << 3) + rin;         // + wn + nfp*16
    const int bCoff = (g8 & 1) << 4;
    uint32_t aOff[4], bOff[2];
#pragma unroll
    for (int mf = 0; mf < 4; mf++)
        aOff[mf] = swz((wm + mf * 16 + aRow) * 128 + aCoff);
#pragma unroll
    for (int nfp = 0; nfp < 2; nfp++)
        bOff[nfp] = A_BYTES_ST + swz((wn + nfp * 16 + bRow) * 128 + bCoff);

    auto issue_stage = [&](int c) {
        const int slot = c % STAGES;
        const uint32_t aBase = sb + slot * STAGE_BYTES;
        const uint32_t bBase = aBase + A_BYTES_ST;
        const uint32_t* Ap = A; int kloc = c * BK;
        if (c >= splitChunk) { Ap = A2; kloc = (c - splitChunk) * BK; }
#pragma unroll
        for (int j = 0; j < 4; j++) {                 // A: 1024 x 16B
            int i = tid + TH * j, m = i >> 3, cc = i & 7;
            cp16(aBase + swz(m * 128 + cc * 16),
                 Ap + (size_t)(bm + m) * Astride + kloc + cc * 4);
        }
#pragma unroll
        for (int j = 0; j < 4; j++) {                 // B: 1024 x 16B
            int i = tid + TH * j, n = i >> 3, cc = i & 7;
            cp16(bBase + swz(n * 128 + cc * 16),
                 Bmat + (size_t)(bn + n) * Bstride + c * BK + cc * 4);
        }
    };

    issue_stage(0); cp_commit();
    issue_stage(1); cp_commit();

    uint32_t af[2][4][4], bfr[2][4][2];

    for (int c = 0; c < Kchunks; c++) {
        cp_wait1();          // stage c arrived (groups G0..Gc done)
        __syncthreads();     // publish stage c; all warps past compute(c-1)
        if (c + 2 < Kchunks) issue_stage(c + 2);
        cp_commit();         // keep group accounting (possibly empty)

        const uint32_t stBase = sb + (c % STAGES) * STAGE_BYTES;

        // prime kk=0 into buffer 0
#pragma unroll
        for (int mf = 0; mf < 4; mf++) ldsm4(af[0][mf], stBase + aOff[mf]);
#pragma unroll
        for (int nfp = 0; nfp < 2; nfp++) {
            uint32_t r[4];
            ldsm4(r, stBase + bOff[nfp]);
            bfr[0][2 * nfp][0] = r[0]; bfr[0][2 * nfp][1] = r[1];
            bfr[0][2 * nfp + 1][0] = r[2]; bfr[0][2 * nfp + 1][1] = r[3];
        }

#pragma unroll
        for (int s = 0; s < 4; s++) {                 // kk = s*8
            const int cur = s & 1, nxt = cur ^ 1;
            if (s < 3) {                              // prefetch kk+1 frags
                const uint32_t d = (uint32_t)(s + 1) * 32;  // (kk+8)*4 bytes
#pragma unroll
                for (int mf = 0; mf < 4; mf++)
                    ldsm4(af[nxt][mf], stBase + (aOff[mf] ^ d));
#pragma unroll
                for (int nfp = 0; nfp < 2; nfp++) {
                    uint32_t r[4];
                    ldsm4(r, stBase + (bOff[nfp] ^ d));
                    bfr[nxt][2 * nfp][0] = r[0]; bfr[nxt][2 * nfp][1] = r[1];
                    bfr[nxt][2 * nfp + 1][0] = r[2]; bfr[nxt][2 * nfp + 1][1] = r[3];
                }
            }
#pragma unroll
            for (int mf = 0; mf < 4; mf++)
#pragma unroll
                for (int nf = 0; nf < 4; nf++)
                    mma_tf32(acc[mf][nf], af[cur][mf], bfr[cur][nf]);
        }
    }

    // ---- epilogue ----
#pragma unroll
    for (int mf = 0; mf < 4; mf++) {
        int r0 = bm + wm + mf * 16 + (lane >> 2);
#pragma unroll
        for (int nf = 0; nf < 4; nf++) {
            int c0 = bn + wn + nf * 8 + ((lane & 3) << 1);
#pragma unroll
            for (int half = 0; half < 2; half++) {
                int r = r0 + 8 * half;
                float d0 = acc[mf][nf][2 * half + 0];
                float d1 = acc[mf][nf][2 * half + 1];
                if (EPI == 0) {
                    float2 bu = *reinterpret_cast<const float2*>(bias + c0);
                    *reinterpret_cast<float2*>((float*)outp + (size_t)r * outStride + c0) =
                        make_float2(d0 + bu.x, d1 + bu.y);
                } else if (EPI == 1) {
                    float2 bc = *reinterpret_cast<const float2*>(bias + c0);
                    float2 rs = *reinterpret_cast<const float2*>(residp + (size_t)r * F + c0);
                    *reinterpret_cast<float2*>((float*)outp + (size_t)r * outStride + c0) =
                        make_float2(fmaxf(d0 + bc.x, 0.f) + rs.x,
                                    fmaxf(d1 + bc.y, 0.f) + rs.y);
                } else {
                    *reinterpret_cast<uint2*>((uint32_t*)outp +
                        (size_t)r * outStride + colOff + c0) =
                        make_uint2(f2tf(d0 * scale), f2tf(d1 * scale));
                }
            }
        }
    }
}

// ============================================================================
// K2: per-row attention over 12 local tokens (HBM-bound streaming pass).
// ============================================================================
__global__ void k2_attn_kernel(const float* __restrict__ gfeat,
                               const float* __restrict__ lfeat,
                               const float* __restrict__ wdr,
                               const float* __restrict__ bdr_p)
{
    const int b = blockIdx.x;
    const int t = threadIdx.x;     // 128
    const int f0 = t * 4;
    const float* lb = lfeat + (size_t)b * NL * F;

    float4 u4 = *reinterpret_cast<const float4*>(&g_U[(size_t)b * F + f0]);

    float4 loc[NL];
    float part[NL];
#pragma unroll
    for (int k = 0; k < NL; k++) {
        loc[k] = *reinterpret_cast<const float4*>(&lb[k * F + f0]);
        part[k] = loc[k].x * u4.x + loc[k].y * u4.y + loc[k].z * u4.z + loc[k].w * u4.w;
    }
#pragma unroll
    for (int k = 0; k < NL; k++) {
#pragma unroll
        for (int o = 16; o > 0; o >>= 1)
            part[k] += __shfl_xor_sync(0xffffffffu, part[k], o);
    }
    __shared__ float red[4][NL];
    const int lane = t & 31, w = t >> 5;
    if (lane == 0) {
#pragma unroll
        for (int k = 0; k < NL; k++) red[w][k] = part[k];
    }
    __syncthreads();

    float a2[NL];
    float m = -1e30f;
#pragma unroll
    for (int k = 0; k < NL; k++) {
        a2[k] = (red[0][k] + red[1][k] + red[2][k] + red[3][k]) * 0.0625f; // 1/sqrt(256)
        m = fmaxf(m, a2[k]);
    }
    float s = 0.f;
#pragma unroll
    for (int k = 0; k < NL; k++) { a2[k] = __expf(a2[k] - m); s += a2[k]; }
    const float inv = 1.f / s;

    float4 pool = make_float4(0.f, 0.f, 0.f, 0.f);
    float4 lfm  = make_float4(0.f, 0.f, 0.f, 0.f);
#pragma unroll
    for (int k = 0; k < NL; k++) {
        float a  = a2[k] * inv;
        float wd = wdr[k];
        pool.x += a * loc[k].x;  pool.y += a * loc[k].y;
        pool.z += a * loc[k].z;  pool.w += a * loc[k].w;
        lfm.x  += wd * loc[k].x; lfm.y  += wd * loc[k].y;
        lfm.z  += wd * loc[k].z; lfm.w  += wd * loc[k].w;
    }
    float4 g4 = *reinterpret_cast<const float4*>(&gfeat[(size_t)b * F + f0]);
    const float bdr = bdr_p[0];
    *reinterpret_cast<float4*>(&g_pooled[(size_t)b * F + f0]) = pool;
    *reinterpret_cast<float4*>(&g_resid[(size_t)b * F + f0]) =
        make_float4(lfm.x + bdr + g4.x, lfm.y + bdr + g4.y,
                    lfm.z + bdr + g4.z, lfm.w + bdr + g4.w);
}

// ============================================================================
extern "C" void kernel_launch(void* const* d_in, const int* in_sizes, int n_in,
                              void* d_out, int out_size)
{
    const float* gfeat = (const float*)d_in[0];
    const float* lfeat = (const float*)d_in[1];
    const float* Wq    = (const float*)d_in[2];
    const float* bq    = (const float*)d_in[3];
    const float* Wk    = (const float*)d_in[4];
    // d_in[5] (bk) cancels in the length-12 softmax.
    const float* Wv    = (const float*)d_in[6];
    const float* bv    = (const float*)d_in[7];
    const float* wdr   = (const float*)d_in[8];
    const float* bdr   = (const float*)d_in[9];
    const float* Wf    = (const float*)d_in[10];
    const float* bf    = (const float*)d_in[11];
    float* out = (float*)d_out;

    const int B = in_sizes[0] / F;   // 16384

    cudaFuncSetAttribute(gemm_mma<0>, cudaFuncAttributeMaxDynamicSharedMemorySize, SMEM_SZ);
    cudaFuncSetAttribute(gemm_mma<1>, cudaFuncAttributeMaxDynamicSharedMemorySize, SMEM_SZ);
    cudaFuncSetAttribute(gemm_mma<2>, cudaFuncAttributeMaxDynamicSharedMemorySize, SMEM_SZ);

    uint32_t* pWu  = nullptr; cudaGetSymbolAddress((void**)&pWu,  g_Wu);
    uint32_t* pWc  = nullptr; cudaGetSymbolAddress((void**)&pWc,  g_Wc);
    float*    pPool= nullptr; cudaGetSymbolAddress((void**)&pPool,g_pooled);
    float*    pU   = nullptr; cudaGetSymbolAddress((void**)&pU,   g_U);
    float*    pRes = nullptr; cudaGetSymbolAddress((void**)&pRes, g_resid);
    float*    pBU  = nullptr; cudaGetSymbolAddress((void**)&pBU,  g_biasU);
    float*    pBC  = nullptr; cudaGetSymbolAddress((void**)&pBC,  g_biasC);

    // --- prep (fp32 bits feed tf32 MMA directly; only Wf needs a transpose) ---
    wf_transpose_kernel<<<dim3(16, 16), dim3(32, 8)>>>(Wf);
    k0_bias_kernel<<<128, 256>>>(Wk, bq, bv, wdr, bdr, bf);

    // weight fusion: z=0 Wu^T, z=1 Wl^T, z=2 Wg^T (scaled by Sw)
    gemm_mma<2><<<dim3(F / BN, F / BM, 3), TH, SMEM_SZ>>>(
        nullptr, nullptr, 0, 0, nullptr, 0, 0, nullptr, 0,
        nullptr, nullptr, wdr,
        (const uint32_t*)Wq, (const uint32_t*)Wk, (const uint32_t*)Wv);

    // GEMM1: U = gfeat @ Wu + b_u   (K=512 -> 16 chunks)
    gemm_mma<0><<<dim3(F / BN, B / BM), TH, SMEM_SZ>>>(
        (const uint32_t*)gfeat, (const uint32_t*)gfeat, 1 << 30, F, pWu, F, F / BK,
        pU, F, pBU, nullptr, nullptr, nullptr, nullptr, nullptr);

    // K2: softmax over 12 locals -> pooled + resid
    k2_attn_kernel<<<B, 128>>>(gfeat, lfeat, wdr, bdr);

    // GEMM2: out = relu([pooled|gfeat] @ Wc + c) + resid  (K=1024 -> 32 chunks)
    gemm_mma<1><<<dim3(F / BN, B / BM), TH, SMEM_SZ>>>(
        (const uint32_t*)pPool, (const uint32_t*)gfeat, F / BK, F, pWc, 2 * F, 2 * F / BK,
        out, F, pBC, pRes, nullptr, nullptr, nullptr, nullptr);
}

// round 15
// speedup vs baseline: 2.4181x; 1.2764x over previous
#include <cuda_runtime.h>
#include <cuda_fp16.h>
#include <cstdint>

// ============================================================================
// ESF_78391743086936 — algebraic restructure + fp16 mma.sync GEMMs (RN).
//   u      = global @ Wu + b_u ;  Wu = Wq Wk^T, b_u = Wk bq   (bk cancels)
//   a2     = softmax_k( (local_k . u) / 16 )
//   pooled = sum_k a2[k] local[k]
//   out    = relu( [pooled|global] @ [Wl;Wg] + c ) + lf_mean + b_dr + global
//   Wl = Wv Wf[:H], Wg = Sw * Wv Wf[H:], c = folded biases, Sw = sum w_dr
// R15: m16n8k16 fp16 (f32 accum) replaces m16n8k8 tf32 — 2x MAC/instr, and
// RN-rounded fp16 inputs are MORE accurate than the tf32-RZ truncation we
// shipped before. BK=64, same SW128 swizzle/ldmatrix/XOR-advance pipeline,
// 3-stage cp.async, double-buffered fragments, 2 CTAs/SM.  No streams.
// ============================================================================

constexpr int F  = 512;
constexpr int H  = 256;
constexpr int NL = 12;
constexpr int MAXB = 16384;

// GEMM tiling: block 128x128, 8 warps (2m x 4n), warp tile 64x32, BK=64 fp16.
constexpr int BM = 128, BN = 128, BK = 64, TH = 256, STAGES = 3;
constexpr int A_BYTES_ST = BM * BK * 2;              // 16384 (128B rows, swizzled)
constexpr int STAGE_BYTES = 2 * A_BYTES_ST;          // 32768
constexpr int SMEM_SZ = STAGES * STAGE_BYTES;        // 98304 -> 2 CTAs/SM

// ---- device scratch ----
__device__ __half  g_gf16[(size_t)MAXB * F];    // gfeat  fp16 (rn)
__device__ __half  g_ph  [(size_t)MAXB * F];    // pooled fp16 (rn)
__device__ float   g_U   [(size_t)MAXB * F];    // u = g@Wu + b_u (fp32)
__device__ float   g_resid[(size_t)MAXB * F];   // lf_mean + b_dr + global
__device__ __half  g_Wu16[F * F];               // [n=f'][k=f] (Wu^T)
__device__ __half  g_Wc16[F * 2 * F];           // [n=f'][0:512 Wl^T | 512:1024 Wg^T]
__device__ __half  g_Wq16[F * H], g_Wk16[F * H], g_Wv16[F * H];
__device__ __half  g_WfT16[F * F];              // WfT[f'][h2] = Wf[h2][f']
__device__ float   g_biasU[F], g_biasC[F];

// ---------------- helpers ----------------
__device__ __forceinline__ uint32_t s2u(const void* p) {
    uint32_t a;
    asm("{ .reg .u64 t; cvta.to.shared.u64 t, %1; cvt.u32.u64 %0, t; }"
        : "=r"(a) : "l"(p));
    return a;
}
__device__ __forceinline__ uint32_t swz(uint32_t b) { return b ^ ((b >> 3) & 0x70); }
__device__ __forceinline__ void cp16(uint32_t dst, const void* src) {
    asm volatile("cp.async.cg.shared.global [%0], [%1], 16;"
                 :: "r"(dst), "l"(src) : "memory");
}
__device__ __forceinline__ void cp_commit() {
    asm volatile("cp.async.commit_group;" ::: "memory");
}
__device__ __forceinline__ void cp_wait1() {
    asm volatile("cp.async.wait_group 1;" ::: "memory");
}
__device__ __forceinline__ void ldsm4(uint32_t* r, uint32_t addr) {
    asm volatile("ldmatrix.sync.aligned.m8n8.x4.shared.b16 {%0,%1,%2,%3}, [%4];"
                 : "=r"(r[0]), "=r"(r[1]), "=r"(r[2]), "=r"(r[3]) : "r"(addr));
}
__device__ __forceinline__ void mma_f16(float* d, const uint32_t* a, const uint32_t* b) {
    asm volatile(
        "mma.sync.aligned.m16n8k16.row.col.f32.f16.f16.f32 "
        "{%0,%1,%2,%3}, {%4,%5,%6,%7}, {%8,%9}, {%0,%1,%2,%3};\n"
        : "+f"(d[0]), "+f"(d[1]), "+f"(d[2]), "+f"(d[3])
        : "r"(a[0]), "r"(a[1]), "r"(a[2]), "r"(a[3]), "r"(b[0]), "r"(b[1]));
}

// ============================================================================
// Prep: fp32 -> fp16 (rn) conversion (generic, reused for gfeat + weights).
// ============================================================================
__global__ void f2h_kernel(const float2* __restrict__ src, __half2* __restrict__ dst, int n2) {
    int i = blockIdx.x * 256 + threadIdx.x;
    if (i < n2) {
        float2 v = src[i];
        dst[i] = __floats2half2_rn(v.x, v.y);
    }
}

// Wf transpose -> fp16: WfT16[f'][h2] = Wf[h2][f'].
__global__ void wf_transpose_kernel(const float* __restrict__ Wf) {
    __shared__ float t[32][33];
    int x = blockIdx.x * 32 + threadIdx.x;          // col f'
    int y0 = blockIdx.y * 32;                       // row h2
    for (int j = threadIdx.y; j < 32; j += 8)
        t[j][threadIdx.x] = Wf[(size_t)(y0 + j) * F + x];
    __syncthreads();
    int xo = blockIdx.y * 32 + threadIdx.x;         // WfT col = h2
    int yo = blockIdx.x * 32;                       // WfT row = f'
    for (int j = threadIdx.y; j < 32; j += 8)
        g_WfT16[(size_t)(yo + j) * F + xo] = __float2half_rn(t[threadIdx.x][j]);
}

// ============================================================================
// Bias vectors, warp-per-output (1024 warps), coalesced.
//   biasU[f] = sum_h Wk[f,h] bq[h]
//   biasC[f] = bf[f] + sum_h bv[h] WfT[f][h] + (Sw bv[h] + bdr) WfT[f][256+h]
// ============================================================================
__global__ void k0_bias_kernel(const float* __restrict__ Wk, const float* __restrict__ bq,
                               const float* __restrict__ bv, const float* __restrict__ wdr,
                               const float* __restrict__ bdr_p, const float* __restrict__ bf)
{
    const int warp = (blockIdx.x * blockDim.x + threadIdx.x) >> 5;
    const int lane = threadIdx.x & 31;
    float s = 0.f;
    if (warp < F) {
        const int f = warp;
#pragma unroll
        for (int i = 0; i < H / 32; i++)
            s += Wk[(size_t)f * H + lane + 32 * i] * bq[lane + 32 * i];
#pragma unroll
        for (int o = 16; o > 0; o >>= 1) s += __shfl_xor_sync(~0u, s, o);
        if (lane == 0) g_biasU[f] = s;
    } else {
        const int f = warp - F;
        float Sw = 0.f;
#pragma unroll
        for (int k = 0; k < NL; k++) Sw += wdr[k];
        const float bdr = bdr_p[0];
#pragma unroll
        for (int i = 0; i < H / 32; i++) {
            int h = lane + 32 * i;
            float w0 = __half2float(g_WfT16[(size_t)f * F + h]);
            float w1 = __half2float(g_WfT16[(size_t)f * F + H + h]);
            s += bv[h] * w0 + (Sw * bv[h] + bdr) * w1;
        }
#pragma unroll
        for (int o = 16; o > 0; o >>= 1) s += __shfl_xor_sync(~0u, s, o);
        if (lane == 0) g_biasC[f] = bf[f] + s;
    }
}

// ============================================================================
// Core GEMM (fp16 in, fp32 acc): C[m][n] = sum_k A[m][k] * B[n][k].
// Block 128x128, warp tile 64x32, BK=64 (4 kk-steps of K=16), ldmatrix
// double-buffered frags, 1 sync/chunk, 3-stage cp.async.
// A split along K: chunk < splitChunk reads A, else A2 (concat [pooled|gfeat]).
// EPI 0: g_U = acc + biasU                 (fp32 out)
// EPI 1: out = relu(acc + biasC) + resid   (final, fp32 out)
// EPI 2: weight fusion (z): z0 Wu^T, z1 Wl^T, z2 Wg^T (x Sw), fp16 out.
// ============================================================================
template<int EPI>
__global__ void __launch_bounds__(TH, 2)
gemm_mma(const __half* __restrict__ A, const __half* __restrict__ A2,
         int splitChunk, int Astride,
         const __half* __restrict__ Bmat, int Bstride, int Kchunks,
         void* __restrict__ outp, int outStride,
         const float* __restrict__ bias, const float* __restrict__ residp,
         const float* __restrict__ wdrp,
         const __half* __restrict__ pWq, const __half* __restrict__ pWk,
         const __half* __restrict__ pWv)
{
    extern __shared__ uint32_t sm[];
    const uint32_t sb = s2u(sm);
    const int tid = threadIdx.x, warp = tid >> 5, lane = tid & 31;
    const int wm = (warp & 1) * 64, wn = (warp >> 1) * 32;
    const int bn = blockIdx.x * BN, bm = blockIdx.y * BM;

    int colOff = 0;
    float scale = 1.f;
    if (EPI == 2) {
        int z = blockIdx.z;
        if (z == 0) { A = pWk; Astride = H; Bmat = pWq;
                      outp = (void*)g_Wu16; outStride = F; }
        else        { A = g_WfT16 + (z == 2 ? H : 0); Astride = F; Bmat = pWv;
                      outp = (void*)g_Wc16; outStride = 2 * F;
                      colOff = (z == 2) ? F : 0; }
        Bstride = H; Kchunks = H / BK; splitChunk = 1 << 30;
        if (z == 2) {
            scale = 0.f;
#pragma unroll
            for (int k = 0; k < NL; k++) scale += wdrp[k];
        }
    }

    float acc[4][4][4];
#pragma unroll
    for (int i = 0; i < 4; i++)
#pragma unroll
        for (int j = 0; j < 4; j++)
#pragma unroll
            for (int v = 0; v < 4; v++) acc[i][j][v] = 0.f;

    // ldmatrix swizzled base offsets; kk advance d in {32,64,96} bytes touches
    // only pre-swizzle bits 5-6 (disjoint from coff bit 4 and row bits), so
    // swz(base + d) == swz(base) ^ d.  (kk-step = 16 fp16 = 32 bytes.)
    const int g8 = lane >> 3, rin = lane & 7;
    const int aRow = ((g8 & 1) << 3) + rin;          // tile m / m+8
    const int aCoff = (g8 >> 1) << 4;                // k-half: 0 / 16B (8 fp16)
    const int bRow = ((g8 >> 1) << 3) + rin;         // tile n / n+8
    const int bCoff = (g8 & 1) << 4;
    uint32_t aOff[4], bOff[2];
#pragma unroll
    for (int mf = 0; mf < 4; mf++)
        aOff[mf] = swz((wm + mf * 16 + aRow) * 128 + aCoff);
#pragma unroll
    for (int nfp = 0; nfp < 2; nfp++)
        bOff[nfp] = A_BYTES_ST + swz((wn + nfp * 16 + bRow) * 128 + bCoff);

    auto issue_stage = [&](int c) {
        const int slot = c % STAGES;
        const uint32_t aBase = sb + slot * STAGE_BYTES;
        const uint32_t bBase = aBase + A_BYTES_ST;
        const __half* Ap = A; int kloc = c * BK;
        if (c >= splitChunk) { Ap = A2; kloc = (c - splitChunk) * BK; }
#pragma unroll
        for (int j = 0; j < 4; j++) {                 // A: 1024 x 16B
            int i = tid + TH * j, m = i >> 3, cc = i & 7;
            cp16(aBase + swz(m * 128 + cc * 16),
                 Ap + (size_t)(bm + m) * Astride + kloc + cc * 8);
        }
#pragma unroll
        for (int j = 0; j < 4; j++) {                 // B: 1024 x 16B
            int i = tid + TH * j, n = i >> 3, cc = i & 7;
            cp16(bBase + swz(n * 128 + cc * 16),
                 Bmat + (size_t)(bn + n) * Bstride + c * BK + cc * 8);
        }
    };

    issue_stage(0); cp_commit();
    issue_stage(1); cp_commit();

    uint32_t af[2][4][4], bfr[2][4][2];

    for (int c = 0; c < Kchunks; c++) {
        cp_wait1();          // stage c arrived (groups G0..Gc done)
        __syncthreads();     // publish stage c; all warps past compute(c-1)
        if (c + 2 < Kchunks) issue_stage(c + 2);
        cp_commit();         // keep group accounting (possibly empty)

        const uint32_t stBase = sb + (c % STAGES) * STAGE_BYTES;

        // prime kk=0 into buffer 0
#pragma unroll
        for (int mf = 0; mf < 4; mf++) ldsm4(af[0][mf], stBase + aOff[mf]);
#pragma unroll
        for (int nfp = 0; nfp < 2; nfp++) {
            uint32_t r[4];
            ldsm4(r, stBase + bOff[nfp]);
            bfr[0][2 * nfp][0] = r[0]; bfr[0][2 * nfp][1] = r[1];
            bfr[0][2 * nfp + 1][0] = r[2]; bfr[0][2 * nfp + 1][1] = r[3];
        }

#pragma unroll
        for (int s = 0; s < 4; s++) {                 // kk = s*16 (fp16)
            const int cur = s & 1, nxt = cur ^ 1;
            if (s < 3) {                              // prefetch kk+1 frags
                const uint32_t d = (uint32_t)(s + 1) * 32;  // bytes
#pragma unroll
                for (int mf = 0; mf < 4; mf++)
                    ldsm4(af[nxt][mf], stBase + (aOff[mf] ^ d));
#pragma unroll
                for (int nfp = 0; nfp < 2; nfp++) {
                    uint32_t r[4];
                    ldsm4(r, stBase + (bOff[nfp] ^ d));
                    bfr[nxt][2 * nfp][0] = r[0]; bfr[nxt][2 * nfp][1] = r[1];
                    bfr[nxt][2 * nfp + 1][0] = r[2]; bfr[nxt][2 * nfp + 1][1] = r[3];
                }
            }
#pragma unroll
            for (int mf = 0; mf < 4; mf++)
#pragma unroll
                for (int nf = 0; nf < 4; nf++)
                    mma_f16(acc[mf][nf], af[cur][mf], bfr[cur][nf]);
        }
    }

    // ---- epilogue ----
#pragma unroll
    for (int mf = 0; mf < 4; mf++) {
        int r0 = bm + wm + mf * 16 + (lane >> 2);
#pragma unroll
        for (int nf = 0; nf < 4; nf++) {
            int c0 = bn + wn + nf * 8 + ((lane & 3) << 1);
#pragma unroll
            for (int half = 0; half < 2; half++) {
                int r = r0 + 8 * half;
                float d0 = acc[mf][nf][2 * half + 0];
                float d1 = acc[mf][nf][2 * half + 1];
                if (EPI == 0) {
                    float2 bu = *reinterpret_cast<const float2*>(bias + c0);
                    *reinterpret_cast<float2*>((float*)outp + (size_t)r * outStride + c0) =
                        make_float2(d0 + bu.x, d1 + bu.y);
                } else if (EPI == 1) {
                    float2 bc = *reinterpret_cast<const float2*>(bias + c0);
                    float2 rs = *reinterpret_cast<const float2*>(residp + (size_t)r * F + c0);
                    *reinterpret_cast<float2*>((float*)outp + (size_t)r * outStride + c0) =
                        make_float2(fmaxf(d0 + bc.x, 0.f) + rs.x,
                                    fmaxf(d1 + bc.y, 0.f) + rs.y);
                } else {
                    *reinterpret_cast<__half2*>((__half*)outp +
                        (size_t)r * outStride + colOff + c0) =
                        __floats2half2_rn(d0 * scale, d1 * scale);
                }
            }
        }
    }
}

// ============================================================================
// K2: per-row attention over 12 local tokens (HBM-bound streaming pass).
// Writes pooled as fp16 (rn) for GEMM2's A operand.
// ============================================================================
__global__ void k2_attn_kernel(const float* __restrict__ gfeat,
                               const float* __restrict__ lfeat,
                               const float* __restrict__ wdr,
                               const float* __restrict__ bdr_p)
{
    const int b = blockIdx.x;
    const int t = threadIdx.x;     // 128
    const int f0 = t * 4;
    const float* lb = lfeat + (size_t)b * NL * F;

    float4 u4 = *reinterpret_cast<const float4*>(&g_U[(size_t)b * F + f0]);

    float4 loc[NL];
    float part[NL];
#pragma unroll
    for (int k = 0; k < NL; k++) {
        loc[k] = *reinterpret_cast<const float4*>(&lb[k * F + f0]);
        part[k] = loc[k].x * u4.x + loc[k].y * u4.y + loc[k].z * u4.z + loc[k].w * u4.w;
    }
#pragma unroll
    for (int k = 0; k < NL; k++) {
#pragma unroll
        for (int o = 16; o > 0; o >>= 1)
            part[k] += __shfl_xor_sync(0xffffffffu, part[k], o);
    }
    __shared__ float red[4][NL];
    const int lane = t & 31, w = t >> 5;
    if (lane == 0) {
#pragma unroll
        for (int k = 0; k < NL; k++) red[w][k] = part[k];
    }
    __syncthreads();

    float a2[NL];
    float m = -1e30f;
#pragma unroll
    for (int k = 0; k < NL; k++) {
        a2[k] = (red[0][k] + red[1][k] + red[2][k] + red[3][k]) * 0.0625f; // 1/sqrt(256)
        m = fmaxf(m, a2[k]);
    }
    float s = 0.f;
#pragma unroll
    for (int k = 0; k < NL; k++) { a2[k] = __expf(a2[k] - m); s += a2[k]; }
    const float inv = 1.f / s;

    float4 pool = make_float4(0.f, 0.f, 0.f, 0.f);
    float4 lfm  = make_float4(0.f, 0.f, 0.f, 0.f);
#pragma unroll
    for (int k = 0; k < NL; k++) {
        float a  = a2[k] * inv;
        float wd = wdr[k];
        pool.x += a * loc[k].x;  pool.y += a * loc[k].y;
        pool.z += a * loc[k].z;  pool.w += a * loc[k].w;
        lfm.x  += wd * loc[k].x; lfm.y  += wd * loc[k].y;
        lfm.z  += wd * loc[k].z; lfm.w  += wd * loc[k].w;
    }
    float4 g4 = *reinterpret_cast<const float4*>(&gfeat[(size_t)b * F + f0]);
    const float bdr = bdr_p[0];
    *reinterpret_cast<__half2*>(&g_ph[(size_t)b * F + f0])     = __floats2half2_rn(pool.x, pool.y);
    *reinterpret_cast<__half2*>(&g_ph[(size_t)b * F + f0 + 2]) = __floats2half2_rn(pool.z, pool.w);
    *reinterpret_cast<float4*>(&g_resid[(size_t)b * F + f0]) =
        make_float4(lfm.x + bdr + g4.x, lfm.y + bdr + g4.y,
                    lfm.z + bdr + g4.z, lfm.w + bdr + g4.w);
}

// ============================================================================
extern "C" void kernel_launch(void* const* d_in, const int* in_sizes, int n_in,
                              void* d_out, int out_size)
{
    const float* gfeat = (const float*)d_in[0];
    const float* lfeat = (const float*)d_in[1];
    const float* Wq    = (const float*)d_in[2];
    const float* bq    = (const float*)d_in[3];
    const float* Wk    = (const float*)d_in[4];
    // d_in[5] (bk) cancels in the length-12 softmax.
    const float* Wv    = (const float*)d_in[6];
    const float* bv    = (const float*)d_in[7];
    const float* wdr   = (const float*)d_in[8];
    const float* bdr   = (const float*)d_in[9];
    const float* Wf    = (const float*)d_in[10];
    const float* bf    = (const float*)d_in[11];
    float* out = (float*)d_out;

    const int B = in_sizes[0] / F;   // 16384

    cudaFuncSetAttribute(gemm_mma<0>, cudaFuncAttributeMaxDynamicSharedMemorySize, SMEM_SZ);
    cudaFuncSetAttribute(gemm_mma<1>, cudaFuncAttributeMaxDynamicSharedMemorySize, SMEM_SZ);
    cudaFuncSetAttribute(gemm_mma<2>, cudaFuncAttributeMaxDynamicSharedMemorySize, SMEM_SZ);

    __half* pGf  = nullptr; cudaGetSymbolAddress((void**)&pGf,  g_gf16);
    __half* pPh  = nullptr; cudaGetSymbolAddress((void**)&pPh,  g_ph);
    __half* pWu  = nullptr; cudaGetSymbolAddress((void**)&pWu,  g_Wu16);
    __half* pWc  = nullptr; cudaGetSymbolAddress((void**)&pWc,  g_Wc16);
    __half* pWq16= nullptr; cudaGetSymbolAddress((void**)&pWq16,g_Wq16);
    __half* pWk16= nullptr; cudaGetSymbolAddress((void**)&pWk16,g_Wk16);
    __half* pWv16= nullptr; cudaGetSymbolAddress((void**)&pWv16,g_Wv16);
    float*  pU   = nullptr; cudaGetSymbolAddress((void**)&pU,   g_U);
    float*  pRes = nullptr; cudaGetSymbolAddress((void**)&pRes, g_resid);
    float*  pBU  = nullptr; cudaGetSymbolAddress((void**)&pBU,  g_biasU);
    float*  pBC  = nullptr; cudaGetSymbolAddress((void**)&pBC,  g_biasC);

    // --- prep: fp16 conversions + Wf transpose + bias vectors ---
    const int ng2 = B * F / 2;
    f2h_kernel<<<(ng2 + 255) / 256, 256>>>((const float2*)gfeat, (__half2*)pGf, ng2);
    const int nw2 = F * H / 2;
    f2h_kernel<<<(nw2 + 255) / 256, 256>>>((const float2*)Wq, (__half2*)pWq16, nw2);
    f2h_kernel<<<(nw2 + 255) / 256, 256>>>((const float2*)Wk, (__half2*)pWk16, nw2);
    f2h_kernel<<<(nw2 + 255) / 256, 256>>>((const float2*)Wv, (__half2*)pWv16, nw2);
    wf_transpose_kernel<<<dim3(16, 16), dim3(32, 8)>>>(Wf);
    k0_bias_kernel<<<128, 256>>>(Wk, bq, bv, wdr, bdr, bf);

    // weight fusion: z=0 Wu^T, z=1 Wl^T, z=2 Wg^T (scaled by Sw); fp16 out
    gemm_mma<2><<<dim3(F / BN, F / BM, 3), TH, SMEM_SZ>>>(
        nullptr, nullptr, 0, 0, nullptr, 0, 0, nullptr, 0,
        nullptr, nullptr, wdr, pWq16, pWk16, pWv16);

    // GEMM1: U = gfeat16 @ Wu + b_u   (K=512 -> 8 chunks)
    gemm_mma<0><<<dim3(F / BN, B / BM), TH, SMEM_SZ>>>(
        pGf, pGf, 1 << 30, F, pWu, F, F / BK,
        pU, F, pBU, nullptr, nullptr, nullptr, nullptr, nullptr);

    // K2: softmax over 12 locals -> pooled (fp16) + resid
    k2_attn_kernel<<<B, 128>>>(gfeat, lfeat, wdr, bdr);

    // GEMM2: out = relu([pooled|gfeat16] @ Wc + c) + resid  (K=1024 -> 16 chunks)
    gemm_mma<1><<<dim3(F / BN, B / BM), TH, SMEM_SZ>>>(
        pPh, pGf, F / BK, F, pWc, 2 * F, 2 * F / BK,
        out, F, pBC, pRes, nullptr, nullptr, nullptr, nullptr);
}